// round 2
// baseline (speedup 1.0000x reference)
#include <cuda_runtime.h>
#include <cuda_bf16.h>
#include <math.h>

// ---------------------------------------------------------------------------
// Problem constants
// ---------------------------------------------------------------------------
#define D_MODEL 1024
#define NHEAD   16
#define HEAD_DIM 64
#define DIM_FF  4096
#define BATCH   4
#define TC      1024
#define TP      1024
#define TK      2048            // TP + TC
#define NROWS   (BATCH * TC)    // 4096
#define EPSF    1e-5f

// ---------------------------------------------------------------------------
// Scratch (global device arrays; no allocations allowed)
// ---------------------------------------------------------------------------
__device__ float g_h  [(size_t)NROWS * D_MODEL];        // LN1 out
__device__ float g_qkv[(size_t)NROWS * 3 * D_MODEL];    // QKV
__device__ float g_o  [(size_t)NROWS * D_MODEL];        // attention out (B,Tc,D)
__device__ float g_x1 [(size_t)NROWS * D_MODEL];        // x + attn proj
__device__ float g_h2 [(size_t)NROWS * D_MODEL];        // LN2 out
__device__ float g_ff [(size_t)NROWS * DIM_FF];         // FFN hidden

// ---------------------------------------------------------------------------
// LayerNorm: one block per row of 1024, 256 threads, float4
// ---------------------------------------------------------------------------
__global__ void ln_kernel(const float* __restrict__ x, const float* __restrict__ g,
                          const float* __restrict__ be, float* __restrict__ out) {
    __shared__ float red[16];
    __shared__ float s_mu, s_rstd;
    const int row = blockIdx.x;
    const int tid = threadIdx.x;
    const float4 v = ((const float4*)(x + (size_t)row * D_MODEL))[tid];
    float s  = v.x + v.y + v.z + v.w;
    float sq = fmaf(v.x, v.x, fmaf(v.y, v.y, fmaf(v.z, v.z, v.w * v.w)));
#pragma unroll
    for (int o = 16; o; o >>= 1) {
        s  += __shfl_xor_sync(0xFFFFFFFFu, s, o);
        sq += __shfl_xor_sync(0xFFFFFFFFu, sq, o);
    }
    const int w = tid >> 5, lane = tid & 31;
    if (lane == 0) { red[w] = s; red[w + 8] = sq; }
    __syncthreads();
    if (tid == 0) {
        float S = 0.f, Q = 0.f;
#pragma unroll
        for (int i = 0; i < 8; i++) { S += red[i]; Q += red[i + 8]; }
        float mu  = S * (1.f / D_MODEL);
        float var = Q * (1.f / D_MODEL) - mu * mu;
        s_mu = mu; s_rstd = rsqrtf(var + EPSF);
    }
    __syncthreads();
    const float mu = s_mu, rstd = s_rstd;
    const float4 gv = ((const float4*)g)[tid];
    const float4 bv = ((const float4*)be)[tid];
    float4 o4;
    o4.x = (v.x - mu) * rstd * gv.x + bv.x;
    o4.y = (v.y - mu) * rstd * gv.y + bv.y;
    o4.z = (v.z - mu) * rstd * gv.z + bv.z;
    o4.w = (v.w - mu) * rstd * gv.w + bv.w;
    ((float4*)(out + (size_t)row * D_MODEL))[tid] = o4;
}

// ---------------------------------------------------------------------------
// SIMT fp32 GEMM: C[M,N] = A[M,K] @ B[K,N] + bias (+res) (gelu optional)
// 128x128 tile, BK=8, 256 threads, 8x8 microtile
// ---------------------------------------------------------------------------
template<bool GELU, bool RES>
__global__ __launch_bounds__(256, 2)
void gemm128(const float* __restrict__ A, const float* __restrict__ B,
             const float* __restrict__ bias, const float* __restrict__ Res,
             float* __restrict__ C, int M, int N, int K) {
    __shared__ float As[8][128];
    __shared__ float Bs[8][132];   // pad keeps 16B alignment (132*4 = 528 = 33*16)
    const int tid = threadIdx.x;
    const int bm = blockIdx.y * 128;
    const int bn = blockIdx.x * 128;
    const int tx = tid & 15;
    const int ty = tid >> 4;
    const int arow = tid >> 1;               // 0..127
    const int akq  = (tid & 1) << 2;         // 0 or 4
    const int brow = tid >> 5;               // 0..7
    const int bcol = (tid & 31) << 2;        // 0..124

    const float* Ap = A + (size_t)(bm + arow) * K + akq;
    const float* Bp = B + (size_t)brow * N + bn + bcol;

    float acc[8][8];
#pragma unroll
    for (int i = 0; i < 8; i++)
#pragma unroll
        for (int j = 0; j < 8; j++) acc[i][j] = 0.f;

    for (int k0 = 0; k0 < K; k0 += 8) {
        const float4 a4 = *(const float4*)(Ap + k0);
        const float4 b4 = *(const float4*)(Bp + (size_t)k0 * N);
        __syncthreads();
        As[akq + 0][arow] = a4.x;
        As[akq + 1][arow] = a4.y;
        As[akq + 2][arow] = a4.z;
        As[akq + 3][arow] = a4.w;
        *(float4*)&Bs[brow][bcol] = b4;
        __syncthreads();
#pragma unroll
        for (int kk = 0; kk < 8; kk++) {
            float a[8], b[8];
            *(float4*)&a[0] = *(const float4*)&As[kk][ty << 3];
            *(float4*)&a[4] = *(const float4*)&As[kk][(ty << 3) + 4];
            *(float4*)&b[0] = *(const float4*)&Bs[kk][tx << 3];
            *(float4*)&b[4] = *(const float4*)&Bs[kk][(tx << 3) + 4];
#pragma unroll
            for (int i = 0; i < 8; i++)
#pragma unroll
                for (int j = 0; j < 8; j++)
                    acc[i][j] = fmaf(a[i], b[j], acc[i][j]);
        }
    }

#pragma unroll
    for (int i = 0; i < 8; i++) {
        const int row = bm + (ty << 3) + i;
        float* cp = C + (size_t)row * N + bn + (tx << 3);
        const float* rp = RES ? (Res + (size_t)row * N + bn + (tx << 3)) : nullptr;
#pragma unroll
        for (int j = 0; j < 8; j++) {
            float v = acc[i][j] + bias[bn + (tx << 3) + j];
            if (GELU) v = 0.5f * v * (1.f + erff(v * 0.70710678118654752f));
            if (RES)  v += rp[j];
            cp[j] = v;
        }
    }
}

// ---------------------------------------------------------------------------
// Build K/V caches in d_out: copy Kp/Vp then scatter new k,v from qkv
// one float4 per thread; first half K, second half V
// ---------------------------------------------------------------------------
__global__ void build_kv(const float* __restrict__ Kp, const float* __restrict__ Vp,
                         const float* __restrict__ qkv,
                         float* __restrict__ outK, float* __restrict__ outV) {
    const size_t PER = (size_t)BATCH * NHEAD * TK * HEAD_DIM / 4;  // 2,097,152
    size_t i = (size_t)blockIdx.x * blockDim.x + threadIdx.x;
    if (i >= 2 * PER) return;
    const int which = i >= PER;           // 0 = K, 1 = V
    const size_t j = which ? (i - PER) : i;
    const size_t rowi = j >> 4;           // (b*H+h)*TK + t
    const int d4 = (int)(j & 15);
    const size_t bh = rowi >> 11;         // /TK
    const int t = (int)(rowi & (TK - 1));
    float4 v;
    if (t < TP) {
        const float* src = (which ? Vp : Kp) + ((bh * TP + t) << 6) + (d4 << 2);
        v = *(const float4*)src;
    } else {
        const int h = (int)(bh & (NHEAD - 1));
        const size_t b = bh >> 4;
        const float* src = qkv + (b * TC + (t - TP)) * (size_t)(3 * D_MODEL)
                               + (which ? 2 * D_MODEL : D_MODEL) + h * HEAD_DIM + (d4 << 2);
        v = *(const float4*)src;
    }
    ((float4*)(which ? outV : outK))[rowi * 16 + d4] = v;
}

// ---------------------------------------------------------------------------
// Flash attention (fp32): block = 64 queries of one (b,h); 256 threads.
// thread t: query row r = t/4, chunk c = t%4 (16 keys / 16 dims).
// ---------------------------------------------------------------------------
#define ATT_PAD 65
#define ATT_SMEM (4 * 64 * ATT_PAD * 4)   // Qs,Ks,Vs,Ps = 66560 bytes
#define BIG_NEG (-1e30f)

__global__ void attn_kernel(const float* __restrict__ qkv, const float* __restrict__ Kc,
                            const float* __restrict__ Vc, const int* __restrict__ pos_ptr,
                            float* __restrict__ O) {
    extern __shared__ float sm[];
    float* Qs = sm;
    float* Ks = Qs + 64 * ATT_PAD;
    float* Vs = Ks + 64 * ATT_PAD;
    float* Ps = Vs + 64 * ATT_PAD;

    const int tid = threadIdx.x;
    const int qb = blockIdx.x;          // 0..15
    const int bh = blockIdx.y;          // 0..63
    const int b = bh >> 4, h = bh & 15;
    const int q0 = qb * 64;
    const int pos = *pos_ptr;
    const int r = tid >> 2;             // query row in tile
    const int c = tid & 3;              // chunk

    // Load Q tile [64][64]
    {
        const float* qsrc = qkv + (size_t)(b * TC + q0 + r) * (3 * D_MODEL)
                                + h * HEAD_DIM + c * 16;
#pragma unroll
        for (int i = 0; i < 16; i += 4) {
            float4 v = *(const float4*)(qsrc + i);
            Qs[r * ATT_PAD + c * 16 + i + 0] = v.x;
            Qs[r * ATT_PAD + c * 16 + i + 1] = v.y;
            Qs[r * ATT_PAD + c * 16 + i + 2] = v.z;
            Qs[r * ATT_PAD + c * 16 + i + 3] = v.w;
        }
    }

    float m_i = BIG_NEG, l_i = 0.f;
    float acc[16];
#pragma unroll
    for (int i = 0; i < 16; i++) acc[i] = 0.f;
    const float scale = 0.125f;                 // 64^-0.5
    const int qi = pos + q0 + r;                // last allowed key for this row
    const int kmax = pos + q0 + 63;
    const size_t kvbase = (size_t)bh * TK * HEAD_DIM;

    for (int kb = 0; kb < TK / 64 && kb * 64 <= kmax; kb++) {
        const int kstart = kb * 64;
        __syncthreads();   // previous iteration's reads done
        {
            const float* ksrc = Kc + kvbase + (size_t)(kstart + r) * HEAD_DIM + c * 16;
            const float* vsrc = Vc + kvbase + (size_t)(kstart + r) * HEAD_DIM + c * 16;
#pragma unroll
            for (int i = 0; i < 16; i += 4) {
                float4 kv4 = *(const float4*)(ksrc + i);
                Ks[r * ATT_PAD + c * 16 + i + 0] = kv4.x;
                Ks[r * ATT_PAD + c * 16 + i + 1] = kv4.y;
                Ks[r * ATT_PAD + c * 16 + i + 2] = kv4.z;
                Ks[r * ATT_PAD + c * 16 + i + 3] = kv4.w;
                float4 vv4 = *(const float4*)(vsrc + i);
                Vs[r * ATT_PAD + c * 16 + i + 0] = vv4.x;
                Vs[r * ATT_PAD + c * 16 + i + 1] = vv4.y;
                Vs[r * ATT_PAD + c * 16 + i + 2] = vv4.z;
                Vs[r * ATT_PAD + c * 16 + i + 3] = vv4.w;
            }
        }
        __syncthreads();

        // scores for keys j in [c*16, c*16+16)
        float p[16];
        float mloc = BIG_NEG;
#pragma unroll
        for (int jj = 0; jj < 16; jj++) {
            const int j = c * 16 + jj;
            float s = 0.f;
#pragma unroll
            for (int dd = 0; dd < 64; dd++)
                s = fmaf(Qs[r * ATT_PAD + dd], Ks[j * ATT_PAD + dd], s);
            s *= scale;
            if (kstart + j > qi) s = BIG_NEG;
            p[jj] = s;
            mloc = fmaxf(mloc, s);
        }
        // max/sum across the 4 lanes sharing row r (consecutive lanes)
        mloc = fmaxf(mloc, __shfl_xor_sync(0xFFFFFFFFu, mloc, 1));
        mloc = fmaxf(mloc, __shfl_xor_sync(0xFFFFFFFFu, mloc, 2));
        const float mnew = fmaxf(m_i, mloc);     // finite: first tile always unmasked
        const float alpha = __expf(m_i - mnew);
        float lsum = 0.f;
#pragma unroll
        for (int jj = 0; jj < 16; jj++) {
            const float e = __expf(p[jj] - mnew); // masked -> exp(-huge) = 0
            Ps[r * ATT_PAD + c * 16 + jj] = e;
            lsum += e;
        }
        lsum += __shfl_xor_sync(0xFFFFFFFFu, lsum, 1);
        lsum += __shfl_xor_sync(0xFFFFFFFFu, lsum, 2);
        l_i = l_i * alpha + lsum;
        m_i = mnew;
#pragma unroll
        for (int d = 0; d < 16; d++) acc[d] *= alpha;
        __syncwarp();
        // O[r][c*16 + di] += sum_j P[r][j] * V[j][c*16+di]
#pragma unroll
        for (int j = 0; j < 64; j++) {
            const float pj = Ps[r * ATT_PAD + j];
#pragma unroll
            for (int di = 0; di < 16; di++)
                acc[di] = fmaf(pj, Vs[j * ATT_PAD + c * 16 + di], acc[di]);
        }
    }

    const float inv = 1.f / l_i;
    float* dst = g_o + (size_t)(b * TC + q0 + r) * D_MODEL + h * HEAD_DIM + c * 16;
#pragma unroll
    for (int di = 0; di < 16; di += 4) {
        float4 v;
        v.x = acc[di + 0] * inv;
        v.y = acc[di + 1] * inv;
        v.z = acc[di + 2] * inv;
        v.w = acc[di + 3] * inv;
        *(float4*)(dst + di) = v;
    }
    (void)O;
}

// ---------------------------------------------------------------------------
// Launch
// ---------------------------------------------------------------------------
extern "C" void kernel_launch(void* const* d_in, const int* in_sizes, int n_in,
                              void* d_out, int out_size) {
    const float* x    = (const float*)d_in[0];
    const float* Kp   = (const float*)d_in[1];
    const float* Vp   = (const float*)d_in[2];
    const int*   posp = (const int*)  d_in[3];
    const float* wqkv = (const float*)d_in[4];
    const float* bqkv = (const float*)d_in[5];
    const float* wo   = (const float*)d_in[6];
    const float* bo   = (const float*)d_in[7];
    const float* g1   = (const float*)d_in[8];
    const float* be1  = (const float*)d_in[9];
    const float* g2   = (const float*)d_in[10];
    const float* be2  = (const float*)d_in[11];
    const float* w1   = (const float*)d_in[12];
    const float* bf1  = (const float*)d_in[13];
    const float* w2   = (const float*)d_in[14];
    const float* bf2  = (const float*)d_in[15];

    float* out_x = (float*)d_out;
    float* out_K = out_x + (size_t)BATCH * TC * D_MODEL;               // +4,194,304
    float* out_V = out_K + (size_t)BATCH * NHEAD * TK * HEAD_DIM;      // +8,388,608

    void* p;
    cudaGetSymbolAddress(&p, g_h);   float* h   = (float*)p;
    cudaGetSymbolAddress(&p, g_qkv); float* qkv = (float*)p;
    cudaGetSymbolAddress(&p, g_o);   float* o   = (float*)p;
    cudaGetSymbolAddress(&p, g_x1);  float* x1  = (float*)p;
    cudaGetSymbolAddress(&p, g_h2);  float* h2  = (float*)p;
    cudaGetSymbolAddress(&p, g_ff);  float* ff  = (float*)p;

    cudaFuncSetAttribute(attn_kernel, cudaFuncAttributeMaxDynamicSharedMemorySize, ATT_SMEM);

    // 1) LN1
    ln_kernel<<<NROWS, 256>>>(x, g1, be1, h);
    // 2) QKV GEMM: [4096,1024] @ [1024,3072]
    gemm128<false, false><<<dim3(3 * D_MODEL / 128, NROWS / 128), 256>>>(
        h, wqkv, bqkv, nullptr, qkv, NROWS, 3 * D_MODEL, D_MODEL);
    // 3) KV cache assembly (writes out_K / out_V)
    build_kv<<<16384, 256>>>(Kp, Vp, qkv, out_K, out_V);
    // 4) Flash attention
    attn_kernel<<<dim3(TC / 64, BATCH * NHEAD), 256, ATT_SMEM>>>(qkv, out_K, out_V, posp, o);
    // 5) O-proj + residual: x1 = x + o@wo + bo
    gemm128<false, true><<<dim3(D_MODEL / 128, NROWS / 128), 256>>>(
        o, wo, bo, x, x1, NROWS, D_MODEL, D_MODEL);
    // 6) LN2
    ln_kernel<<<NROWS, 256>>>(x1, g2, be2, h2);
    // 7) FFN1 + GELU: [4096,1024]@[1024,4096]
    gemm128<true, false><<<dim3(DIM_FF / 128, NROWS / 128), 256>>>(
        h2, w1, bf1, nullptr, ff, NROWS, DIM_FF, D_MODEL);
    // 8) FFN2 + residual -> out_x: [4096,4096]@[4096,1024]
    gemm128<false, true><<<dim3(D_MODEL / 128, NROWS / 128), 256>>>(
        ff, w2, bf2, x1, out_x, NROWS, D_MODEL, DIM_FF);
}

// round 4
// speedup vs baseline: 1.3010x; 1.3010x over previous
#include <cuda_runtime.h>
#include <cuda_bf16.h>
#include <math.h>
#include <stdint.h>

// ---------------------------------------------------------------------------
// Problem constants
// ---------------------------------------------------------------------------
#define D_MODEL 1024
#define NHEAD   16
#define HEAD_DIM 64
#define DIM_FF  4096
#define BATCH   4
#define TC      1024
#define TP      1024
#define TK      2048
#define NROWS   (BATCH * TC)    // 4096
#define EPSF    1e-5f

// ---------------------------------------------------------------------------
// Scratch (device globals; no allocations allowed)
// ---------------------------------------------------------------------------
__device__ float          g_qkv  [(size_t)NROWS * 3 * D_MODEL];
__device__ float          g_x1   [(size_t)NROWS * D_MODEL];
__device__ __nv_bfloat16  g_h_hi [(size_t)NROWS * D_MODEL];
__device__ __nv_bfloat16  g_h_lo [(size_t)NROWS * D_MODEL];
__device__ __nv_bfloat16  g_o_hi [(size_t)NROWS * D_MODEL];
__device__ __nv_bfloat16  g_o_lo [(size_t)NROWS * D_MODEL];
__device__ __nv_bfloat16  g_h2_hi[(size_t)NROWS * D_MODEL];
__device__ __nv_bfloat16  g_h2_lo[(size_t)NROWS * D_MODEL];
__device__ __nv_bfloat16  g_ff_hi[(size_t)NROWS * DIM_FF];
__device__ __nv_bfloat16  g_ff_lo[(size_t)NROWS * DIM_FF];
// transposed-split weights [N,K]
__device__ __nv_bfloat16  g_wqkvT_hi[(size_t)3 * D_MODEL * D_MODEL];
__device__ __nv_bfloat16  g_wqkvT_lo[(size_t)3 * D_MODEL * D_MODEL];
__device__ __nv_bfloat16  g_woT_hi  [(size_t)D_MODEL * D_MODEL];
__device__ __nv_bfloat16  g_woT_lo  [(size_t)D_MODEL * D_MODEL];
__device__ __nv_bfloat16  g_w1T_hi  [(size_t)DIM_FF * D_MODEL];
__device__ __nv_bfloat16  g_w1T_lo  [(size_t)DIM_FF * D_MODEL];
__device__ __nv_bfloat16  g_w2T_hi  [(size_t)D_MODEL * DIM_FF];
__device__ __nv_bfloat16  g_w2T_lo  [(size_t)D_MODEL * DIM_FF];

// ---------------------------------------------------------------------------
// Helpers
// ---------------------------------------------------------------------------
__device__ __forceinline__ uint32_t s2u(const void* p) {
    uint32_t a;
    asm("{ .reg .u64 t; cvta.to.shared.u64 t, %1; cvt.u32.u64 %0, t; }" : "=r"(a) : "l"(p));
    return a;
}
__device__ __forceinline__ void cp16(uint32_t dst, const void* src) {
    asm volatile("cp.async.cg.shared.global [%0], [%1], 16;" :: "r"(dst), "l"(src));
}
#define CP_COMMIT() asm volatile("cp.async.commit_group;" ::: "memory")
#define CP_WAIT(n)  asm volatile("cp.async.wait_group %0;" :: "n"(n) : "memory")

__device__ __forceinline__ void ldsm4(uint32_t* r, uint32_t addr) {
    asm volatile("ldmatrix.sync.aligned.m8n8.x4.shared.b16 {%0,%1,%2,%3}, [%4];"
                 : "=r"(r[0]), "=r"(r[1]), "=r"(r[2]), "=r"(r[3]) : "r"(addr));
}
__device__ __forceinline__ void ldsm2(uint32_t* r, uint32_t addr) {
    asm volatile("ldmatrix.sync.aligned.m8n8.x2.shared.b16 {%0,%1}, [%2];"
                 : "=r"(r[0]), "=r"(r[1]) : "r"(addr));
}
__device__ __forceinline__ void mma16816(float* d, const uint32_t* a, const uint32_t* b) {
    asm volatile(
        "mma.sync.aligned.m16n8k16.row.col.f32.bf16.bf16.f32 "
        "{%0,%1,%2,%3}, {%4,%5,%6,%7}, {%8,%9}, {%0,%1,%2,%3};"
        : "+f"(d[0]), "+f"(d[1]), "+f"(d[2]), "+f"(d[3])
        : "r"(a[0]), "r"(a[1]), "r"(a[2]), "r"(a[3]), "r"(b[0]), "r"(b[1]));
}

// ---------------------------------------------------------------------------
// LayerNorm -> split bf16 hi/lo
// ---------------------------------------------------------------------------
__global__ void ln_split_kernel(const float* __restrict__ x, const float* __restrict__ g,
                                const float* __restrict__ be,
                                __nv_bfloat16* __restrict__ hi, __nv_bfloat16* __restrict__ lo) {
    __shared__ float red[16];
    __shared__ float s_mu, s_rstd;
    const int row = blockIdx.x;
    const int tid = threadIdx.x;
    const float4 v = ((const float4*)(x + (size_t)row * D_MODEL))[tid];
    float s  = v.x + v.y + v.z + v.w;
    float sq = fmaf(v.x, v.x, fmaf(v.y, v.y, fmaf(v.z, v.z, v.w * v.w)));
#pragma unroll
    for (int o = 16; o; o >>= 1) {
        s  += __shfl_xor_sync(0xFFFFFFFFu, s, o);
        sq += __shfl_xor_sync(0xFFFFFFFFu, sq, o);
    }
    const int w = tid >> 5, lane = tid & 31;
    if (lane == 0) { red[w] = s; red[w + 8] = sq; }
    __syncthreads();
    if (tid == 0) {
        float S = 0.f, Q = 0.f;
#pragma unroll
        for (int i = 0; i < 8; i++) { S += red[i]; Q += red[i + 8]; }
        float mu  = S * (1.f / D_MODEL);
        float var = Q * (1.f / D_MODEL) - mu * mu;
        s_mu = mu; s_rstd = rsqrtf(var + EPSF);
    }
    __syncthreads();
    const float mu = s_mu, rstd = s_rstd;
    const float4 gv = ((const float4*)g)[tid];
    const float4 bv = ((const float4*)be)[tid];
    float o4[4];
    o4[0] = (v.x - mu) * rstd * gv.x + bv.x;
    o4[1] = (v.y - mu) * rstd * gv.y + bv.y;
    o4[2] = (v.z - mu) * rstd * gv.z + bv.z;
    o4[3] = (v.w - mu) * rstd * gv.w + bv.w;
    __nv_bfloat162* hp = (__nv_bfloat162*)(hi + (size_t)row * D_MODEL) + tid * 2;
    __nv_bfloat162* lp = (__nv_bfloat162*)(lo + (size_t)row * D_MODEL) + tid * 2;
#pragma unroll
    for (int j = 0; j < 2; j++) {
        __nv_bfloat16 h0 = __float2bfloat16(o4[2 * j]);
        __nv_bfloat16 h1 = __float2bfloat16(o4[2 * j + 1]);
        __nv_bfloat16 l0 = __float2bfloat16(o4[2 * j]     - __bfloat162float(h0));
        __nv_bfloat16 l1 = __float2bfloat16(o4[2 * j + 1] - __bfloat162float(h1));
        hp[j] = __nv_bfloat162(h0, h1);
        lp[j] = __nv_bfloat162(l0, l1);
    }
}

// ---------------------------------------------------------------------------
// Weight transpose + split: W[K,N] fp32 -> T_hi/T_lo [N,K] bf16
// ---------------------------------------------------------------------------
__global__ void transpose_split(const float* __restrict__ W,
                                __nv_bfloat16* __restrict__ hi, __nv_bfloat16* __restrict__ lo,
                                int K, int N) {
    __shared__ float t[32][33];
    const int k0 = blockIdx.y * 32, n0 = blockIdx.x * 32;
    const int tx = threadIdx.x & 31, ty = threadIdx.x >> 5;
#pragma unroll
    for (int i = 0; i < 32; i += 8)
        t[ty + i][tx] = W[(size_t)(k0 + ty + i) * N + n0 + tx];
    __syncthreads();
#pragma unroll
    for (int i = 0; i < 32; i += 8) {
        float v = t[tx][ty + i];
        __nv_bfloat16 h = __float2bfloat16(v);
        __nv_bfloat16 l = __float2bfloat16(v - __bfloat162float(h));
        hi[(size_t)(n0 + ty + i) * K + k0 + tx] = h;
        lo[(size_t)(n0 + ty + i) * K + k0 + tx] = l;
    }
}

// ---------------------------------------------------------------------------
// mma.sync bf16 split GEMM: C[M,N] = A[M,K] @ Bt[N,K]^T (3 MMA terms)
// CTA 128x128, BK=32, cp.async double buffer, 8 warps (warp tile 64x32).
// SMEM rows padded to 80B -> conflict-free ldmatrix.
// EPI: 0 = +bias -> fp32 C; 1 = +bias+res -> fp32 C; 2 = +bias,gelu -> split hi/lo
// ---------------------------------------------------------------------------
#define TPAD_B   80                      // bytes per smem row (32 bf16 + pad)
#define TILE_B   (128 * TPAD_B)          // 10240 bytes per matrix tile
#define BUF_B    (4 * TILE_B)            // Ah, Al, Bh, Bl
#define GM_SMEM  (2 * BUF_B)             // 81920

template<int EPI>
__global__ __launch_bounds__(256, 1)
void gemm_mma(const __nv_bfloat16* __restrict__ Ahi, const __nv_bfloat16* __restrict__ Alo,
              const __nv_bfloat16* __restrict__ Bhi, const __nv_bfloat16* __restrict__ Blo,
              const float* __restrict__ bias, const float* __restrict__ Res,
              float* __restrict__ C, __nv_bfloat16* __restrict__ Chi, __nv_bfloat16* __restrict__ Clo,
              int N, int K) {
    extern __shared__ char smc[];
    const uint32_t sb = s2u(smc);
    const int tid  = threadIdx.x;
    const int lane = tid & 31;
    const int wid  = tid >> 5;
    const int wm   = wid >> 2;            // 0..1
    const int wn   = wid & 3;             // 0..3
    const int bm = blockIdx.y * 128;
    const int bn = blockIdx.x * 128;

    const __nv_bfloat16* src0 = Ahi + (size_t)bm * K;
    const __nv_bfloat16* src1 = Alo + (size_t)bm * K;
    const __nv_bfloat16* src2 = Bhi + (size_t)bn * K;
    const __nv_bfloat16* src3 = Blo + (size_t)bn * K;

    const int r0 = tid >> 2,        c0 = tid & 3;          // chunk tid
    const int r1 = (tid + 256) >> 2, c1 = tid & 3;         // chunk tid+256

#define PREFETCH(kb, buf)                                                          \
    do {                                                                           \
        const uint32_t db = sb + (buf) * BUF_B;                                    \
        const int ko = (kb) * 32;                                                  \
        cp16(db + 0*TILE_B + r0*TPAD_B + c0*16, (const char*)(src0 + (size_t)r0*K + ko) + c0*16); \
        cp16(db + 0*TILE_B + r1*TPAD_B + c1*16, (const char*)(src0 + (size_t)r1*K + ko) + c1*16); \
        cp16(db + 1*TILE_B + r0*TPAD_B + c0*16, (const char*)(src1 + (size_t)r0*K + ko) + c0*16); \
        cp16(db + 1*TILE_B + r1*TPAD_B + c1*16, (const char*)(src1 + (size_t)r1*K + ko) + c1*16); \
        cp16(db + 2*TILE_B + r0*TPAD_B + c0*16, (const char*)(src2 + (size_t)r0*K + ko) + c0*16); \
        cp16(db + 2*TILE_B + r1*TPAD_B + c1*16, (const char*)(src2 + (size_t)r1*K + ko) + c1*16); \
        cp16(db + 3*TILE_B + r0*TPAD_B + c0*16, (const char*)(src3 + (size_t)r0*K + ko) + c0*16); \
        cp16(db + 3*TILE_B + r1*TPAD_B + c1*16, (const char*)(src3 + (size_t)r1*K + ko) + c1*16); \
        CP_COMMIT();                                                               \
    } while (0)

    float acc[4][4][4];
#pragma unroll
    for (int m = 0; m < 4; m++)
#pragma unroll
        for (int n = 0; n < 4; n++)
#pragma unroll
            for (int i = 0; i < 4; i++) acc[m][n][i] = 0.f;

    const int NKB = K >> 5;
    PREFETCH(0, 0);

    for (int kb = 0; kb < NKB; kb++) {
        if (kb + 1 < NKB) { PREFETCH(kb + 1, (kb + 1) & 1); CP_WAIT(1); }
        else              { CP_WAIT(0); }
        __syncthreads();

        const uint32_t b  = sb + (kb & 1) * BUF_B;
        const uint32_t Ah = b, Al = b + TILE_B, Bh = b + 2 * TILE_B, Bl = b + 3 * TILE_B;
#pragma unroll
        for (int ks = 0; ks < 2; ks++) {
            uint32_t ah[4][4], al[4][4], bh[4][2], bl[4][2];
            const uint32_t aoff = (uint32_t)(wm * 64 + (lane & 15)) * TPAD_B + ks * 32 + (lane >> 4) * 16;
            const uint32_t boff = (uint32_t)(wn * 32 + (lane & 7)) * TPAD_B + ks * 32 + ((lane >> 3) & 1) * 16;
#pragma unroll
            for (int m = 0; m < 4; m++) {
                ldsm4(ah[m], Ah + aoff + m * 16 * TPAD_B);
                ldsm4(al[m], Al + aoff + m * 16 * TPAD_B);
            }
#pragma unroll
            for (int n = 0; n < 4; n++) {
                ldsm2(bh[n], Bh + boff + n * 8 * TPAD_B);
                ldsm2(bl[n], Bl + boff + n * 8 * TPAD_B);
            }
#pragma unroll
            for (int m = 0; m < 4; m++)
#pragma unroll
                for (int n = 0; n < 4; n++) {
                    mma16816(acc[m][n], ah[m], bh[n]);
                    mma16816(acc[m][n], al[m], bh[n]);
                    mma16816(acc[m][n], ah[m], bl[n]);
                }
        }
        __syncthreads();
    }

    // epilogue
#pragma unroll
    for (int m = 0; m < 4; m++)
#pragma unroll
        for (int n = 0; n < 4; n++) {
            const int col  = bn + wn * 32 + n * 8 + 2 * (lane & 3);
            const float b0 = bias[col], b1 = bias[col + 1];
#pragma unroll
            for (int half = 0; half < 2; half++) {
                const int row = bm + wm * 64 + m * 16 + (lane >> 2) + half * 8;
                float v0 = acc[m][n][2 * half]     + b0;
                float v1 = acc[m][n][2 * half + 1] + b1;
                if (EPI == 2) {
                    v0 = 0.5f * v0 * (1.f + erff(v0 * 0.70710678118654752f));
                    v1 = 0.5f * v1 * (1.f + erff(v1 * 0.70710678118654752f));
                    __nv_bfloat16 h0 = __float2bfloat16(v0);
                    __nv_bfloat16 h1 = __float2bfloat16(v1);
                    __nv_bfloat16 l0 = __float2bfloat16(v0 - __bfloat162float(h0));
                    __nv_bfloat16 l1 = __float2bfloat16(v1 - __bfloat162float(h1));
                    *(__nv_bfloat162*)(Chi + (size_t)row * N + col) = __nv_bfloat162(h0, h1);
                    *(__nv_bfloat162*)(Clo + (size_t)row * N + col) = __nv_bfloat162(l0, l1);
                } else {
                    if (EPI == 1) {
                        const float2 rv = *(const float2*)(Res + (size_t)row * N + col);
                        v0 += rv.x; v1 += rv.y;
                    }
                    float2 o2; o2.x = v0; o2.y = v1;
                    *(float2*)(C + (size_t)row * N + col) = o2;
                }
            }
        }
#undef PREFETCH
}

// ---------------------------------------------------------------------------
// Build K/V caches in d_out
// ---------------------------------------------------------------------------
__global__ void build_kv(const float* __restrict__ Kp, const float* __restrict__ Vp,
                         const float* __restrict__ qkv,
                         float* __restrict__ outK, float* __restrict__ outV) {
    const size_t PER = (size_t)BATCH * NHEAD * TK * HEAD_DIM / 4;
    size_t i = (size_t)blockIdx.x * blockDim.x + threadIdx.x;
    if (i >= 2 * PER) return;
    const int which = i >= PER;
    const size_t j = which ? (i - PER) : i;
    const size_t rowi = j >> 4;
    const int d4 = (int)(j & 15);
    const size_t bh = rowi >> 11;
    const int t = (int)(rowi & (TK - 1));
    float4 v;
    if (t < TP) {
        const float* src = (which ? Vp : Kp) + ((bh * TP + t) << 6) + (d4 << 2);
        v = *(const float4*)src;
    } else {
        const int h = (int)(bh & (NHEAD - 1));
        const size_t b = bh >> 4;
        const float* src = qkv + (b * TC + (t - TP)) * (size_t)(3 * D_MODEL)
                               + (which ? 2 * D_MODEL : D_MODEL) + h * HEAD_DIM + (d4 << 2);
        v = *(const float4*)src;
    }
    ((float4*)(which ? outV : outK))[rowi * 16 + d4] = v;
}

// ---------------------------------------------------------------------------
// Flash attention (fp32), split bf16 epilogue
// ---------------------------------------------------------------------------
#define ATT_PAD 65
#define ATT_SMEM (4 * 64 * ATT_PAD * 4)
#define BIG_NEG (-1e30f)

__global__ void attn_kernel(const float* __restrict__ qkv, const float* __restrict__ Kc,
                            const float* __restrict__ Vc, const int* __restrict__ pos_ptr) {
    extern __shared__ float smf[];
    float* Qs = smf;
    float* Ks = Qs + 64 * ATT_PAD;
    float* Vs = Ks + 64 * ATT_PAD;
    float* Ps = Vs + 64 * ATT_PAD;

    const int tid = threadIdx.x;
    const int qb = blockIdx.x;
    const int bh = blockIdx.y;
    const int b = bh >> 4, h = bh & 15;
    const int q0 = qb * 64;
    const int pos = *pos_ptr;
    const int r = tid >> 2;
    const int c = tid & 3;

    {
        const float* qsrc = qkv + (size_t)(b * TC + q0 + r) * (3 * D_MODEL)
                                + h * HEAD_DIM + c * 16;
#pragma unroll
        for (int i = 0; i < 16; i += 4) {
            float4 v = *(const float4*)(qsrc + i);
            Qs[r * ATT_PAD + c * 16 + i + 0] = v.x;
            Qs[r * ATT_PAD + c * 16 + i + 1] = v.y;
            Qs[r * ATT_PAD + c * 16 + i + 2] = v.z;
            Qs[r * ATT_PAD + c * 16 + i + 3] = v.w;
        }
    }

    float m_i = BIG_NEG, l_i = 0.f;
    float acc[16];
#pragma unroll
    for (int i = 0; i < 16; i++) acc[i] = 0.f;
    const float scale = 0.125f;
    const int qi = pos + q0 + r;
    const int kmax = pos + q0 + 63;
    const size_t kvbase = (size_t)bh * TK * HEAD_DIM;

    for (int kb = 0; kb < TK / 64 && kb * 64 <= kmax; kb++) {
        const int kstart = kb * 64;
        __syncthreads();
        {
            const float* ksrc = Kc + kvbase + (size_t)(kstart + r) * HEAD_DIM + c * 16;
            const float* vsrc = Vc + kvbase + (size_t)(kstart + r) * HEAD_DIM + c * 16;
#pragma unroll
            for (int i = 0; i < 16; i += 4) {
                float4 kv4 = *(const float4*)(ksrc + i);
                Ks[r * ATT_PAD + c * 16 + i + 0] = kv4.x;
                Ks[r * ATT_PAD + c * 16 + i + 1] = kv4.y;
                Ks[r * ATT_PAD + c * 16 + i + 2] = kv4.z;
                Ks[r * ATT_PAD + c * 16 + i + 3] = kv4.w;
                float4 vv4 = *(const float4*)(vsrc + i);
                Vs[r * ATT_PAD + c * 16 + i + 0] = vv4.x;
                Vs[r * ATT_PAD + c * 16 + i + 1] = vv4.y;
                Vs[r * ATT_PAD + c * 16 + i + 2] = vv4.z;
                Vs[r * ATT_PAD + c * 16 + i + 3] = vv4.w;
            }
        }
        __syncthreads();

        float p[16];
        float mloc = BIG_NEG;
#pragma unroll
        for (int jj = 0; jj < 16; jj++) {
            const int j = c * 16 + jj;
            float s = 0.f;
#pragma unroll
            for (int dd = 0; dd < 64; dd++)
                s = fmaf(Qs[r * ATT_PAD + dd], Ks[j * ATT_PAD + dd], s);
            s *= scale;
            if (kstart + j > qi) s = BIG_NEG;
            p[jj] = s;
            mloc = fmaxf(mloc, s);
        }
        mloc = fmaxf(mloc, __shfl_xor_sync(0xFFFFFFFFu, mloc, 1));
        mloc = fmaxf(mloc, __shfl_xor_sync(0xFFFFFFFFu, mloc, 2));
        const float mnew = fmaxf(m_i, mloc);
        const float alpha = __expf(m_i - mnew);
        float lsum = 0.f;
#pragma unroll
        for (int jj = 0; jj < 16; jj++) {
            const float e = __expf(p[jj] - mnew);
            Ps[r * ATT_PAD + c * 16 + jj] = e;
            lsum += e;
        }
        lsum += __shfl_xor_sync(0xFFFFFFFFu, lsum, 1);
        lsum += __shfl_xor_sync(0xFFFFFFFFu, lsum, 2);
        l_i = l_i * alpha + lsum;
        m_i = mnew;
#pragma unroll
        for (int d = 0; d < 16; d++) acc[d] *= alpha;
        __syncwarp();
#pragma unroll
        for (int j = 0; j < 64; j++) {
            const float pj = Ps[r * ATT_PAD + j];
#pragma unroll
            for (int di = 0; di < 16; di++)
                acc[di] = fmaf(pj, Vs[j * ATT_PAD + c * 16 + di], acc[di]);
        }
    }

    const float inv = 1.f / l_i;
    const size_t obase = (size_t)(b * TC + q0 + r) * D_MODEL + h * HEAD_DIM + c * 16;
    __nv_bfloat162* hp = (__nv_bfloat162*)(g_o_hi + obase);
    __nv_bfloat162* lp = (__nv_bfloat162*)(g_o_lo + obase);
#pragma unroll
    for (int di = 0; di < 16; di += 2) {
        const float v0 = acc[di] * inv;
        const float v1 = acc[di + 1] * inv;
        __nv_bfloat16 h0 = __float2bfloat16(v0);
        __nv_bfloat16 h1 = __float2bfloat16(v1);
        __nv_bfloat16 l0 = __float2bfloat16(v0 - __bfloat162float(h0));
        __nv_bfloat16 l1 = __float2bfloat16(v1 - __bfloat162float(h1));
        hp[di >> 1] = __nv_bfloat162(h0, h1);
        lp[di >> 1] = __nv_bfloat162(l0, l1);
    }
}

// ---------------------------------------------------------------------------
// Launch
// ---------------------------------------------------------------------------
extern "C" void kernel_launch(void* const* d_in, const int* in_sizes, int n_in,
                              void* d_out, int out_size) {
    const float* x    = (const float*)d_in[0];
    const float* Kp   = (const float*)d_in[1];
    const float* Vp   = (const float*)d_in[2];
    const int*   posp = (const int*)  d_in[3];
    const float* wqkv = (const float*)d_in[4];
    const float* bqkv = (const float*)d_in[5];
    const float* wo   = (const float*)d_in[6];
    const float* bo   = (const float*)d_in[7];
    const float* g1   = (const float*)d_in[8];
    const float* be1  = (const float*)d_in[9];
    const float* g2   = (const float*)d_in[10];
    const float* be2  = (const float*)d_in[11];
    const float* w1   = (const float*)d_in[12];
    const float* bf1  = (const float*)d_in[13];
    const float* w2   = (const float*)d_in[14];
    const float* bf2  = (const float*)d_in[15];

    float* out_x = (float*)d_out;
    float* out_K = out_x + (size_t)BATCH * TC * D_MODEL;
    float* out_V = out_K + (size_t)BATCH * NHEAD * TK * HEAD_DIM;

    void* p;
    cudaGetSymbolAddress(&p, g_qkv);      float* qkv = (float*)p;
    cudaGetSymbolAddress(&p, g_x1);       float* x1  = (float*)p;
    cudaGetSymbolAddress(&p, g_h_hi);     __nv_bfloat16* hhi = (__nv_bfloat16*)p;
    cudaGetSymbolAddress(&p, g_h_lo);     __nv_bfloat16* hlo = (__nv_bfloat16*)p;
    cudaGetSymbolAddress(&p, g_o_hi);     __nv_bfloat16* ohi = (__nv_bfloat16*)p;
    cudaGetSymbolAddress(&p, g_o_lo);     __nv_bfloat16* olo = (__nv_bfloat16*)p;
    cudaGetSymbolAddress(&p, g_h2_hi);    __nv_bfloat16* h2hi = (__nv_bfloat16*)p;
    cudaGetSymbolAddress(&p, g_h2_lo);    __nv_bfloat16* h2lo = (__nv_bfloat16*)p;
    cudaGetSymbolAddress(&p, g_ff_hi);    __nv_bfloat16* ffhi = (__nv_bfloat16*)p;
    cudaGetSymbolAddress(&p, g_ff_lo);    __nv_bfloat16* fflo = (__nv_bfloat16*)p;
    cudaGetSymbolAddress(&p, g_wqkvT_hi); __nv_bfloat16* wqkvThi = (__nv_bfloat16*)p;
    cudaGetSymbolAddress(&p, g_wqkvT_lo); __nv_bfloat16* wqkvTlo = (__nv_bfloat16*)p;
    cudaGetSymbolAddress(&p, g_woT_hi);   __nv_bfloat16* woThi = (__nv_bfloat16*)p;
    cudaGetSymbolAddress(&p, g_woT_lo);   __nv_bfloat16* woTlo = (__nv_bfloat16*)p;
    cudaGetSymbolAddress(&p, g_w1T_hi);   __nv_bfloat16* w1Thi = (__nv_bfloat16*)p;
    cudaGetSymbolAddress(&p, g_w1T_lo);   __nv_bfloat16* w1Tlo = (__nv_bfloat16*)p;
    cudaGetSymbolAddress(&p, g_w2T_hi);   __nv_bfloat16* w2Thi = (__nv_bfloat16*)p;
    cudaGetSymbolAddress(&p, g_w2T_lo);   __nv_bfloat16* w2Tlo = (__nv_bfloat16*)p;

    cudaFuncSetAttribute(attn_kernel, cudaFuncAttributeMaxDynamicSharedMemorySize, ATT_SMEM);
    cudaFuncSetAttribute(gemm_mma<0>, cudaFuncAttributeMaxDynamicSharedMemorySize, GM_SMEM);
    cudaFuncSetAttribute(gemm_mma<1>, cudaFuncAttributeMaxDynamicSharedMemorySize, GM_SMEM);
    cudaFuncSetAttribute(gemm_mma<2>, cudaFuncAttributeMaxDynamicSharedMemorySize, GM_SMEM);

    // 0) weight transpose + split
    transpose_split<<<dim3(3 * D_MODEL / 32, D_MODEL / 32), 256>>>(wqkv, wqkvThi, wqkvTlo, D_MODEL, 3 * D_MODEL);
    transpose_split<<<dim3(D_MODEL / 32, D_MODEL / 32), 256>>>(wo, woThi, woTlo, D_MODEL, D_MODEL);
    transpose_split<<<dim3(DIM_FF / 32, D_MODEL / 32), 256>>>(w1, w1Thi, w1Tlo, D_MODEL, DIM_FF);
    transpose_split<<<dim3(D_MODEL / 32, DIM_FF / 32), 256>>>(w2, w2Thi, w2Tlo, DIM_FF, D_MODEL);
    // 1) LN1 -> split
    ln_split_kernel<<<NROWS, 256>>>(x, g1, be1, hhi, hlo);
    // 2) QKV GEMM
    gemm_mma<0><<<dim3(3 * D_MODEL / 128, NROWS / 128), 256, GM_SMEM>>>(
        hhi, hlo, wqkvThi, wqkvTlo, bqkv, nullptr, qkv, nullptr, nullptr, 3 * D_MODEL, D_MODEL);
    // 3) KV cache assembly
    build_kv<<<16384, 256>>>(Kp, Vp, qkv, out_K, out_V);
    // 4) Flash attention -> o hi/lo
    attn_kernel<<<dim3(TC / 64, BATCH * NHEAD), 256, ATT_SMEM>>>(qkv, out_K, out_V, posp);
    // 5) O-proj + residual -> x1
    gemm_mma<1><<<dim3(D_MODEL / 128, NROWS / 128), 256, GM_SMEM>>>(
        ohi, olo, woThi, woTlo, bo, x, x1, nullptr, nullptr, D_MODEL, D_MODEL);
    // 6) LN2 -> split
    ln_split_kernel<<<NROWS, 256>>>(x1, g2, be2, h2hi, h2lo);
    // 7) FFN1 + GELU -> ff hi/lo
    gemm_mma<2><<<dim3(DIM_FF / 128, NROWS / 128), 256, GM_SMEM>>>(
        h2hi, h2lo, w1Thi, w1Tlo, bf1, nullptr, nullptr, ffhi, fflo, DIM_FF, D_MODEL);
    // 8) FFN2 + residual -> out_x
    gemm_mma<1><<<dim3(D_MODEL / 128, NROWS / 128), 256, GM_SMEM>>>(
        ffhi, fflo, w2Thi, w2Tlo, bf2, x1, out_x, nullptr, nullptr, D_MODEL, DIM_FF);
}

// round 5
// speedup vs baseline: 3.9531x; 3.0385x over previous
#include <cuda_runtime.h>
#include <cuda_bf16.h>
#include <math.h>
#include <stdint.h>

// ---------------------------------------------------------------------------
// Problem constants
// ---------------------------------------------------------------------------
#define D_MODEL 1024
#define NHEAD   16
#define HEAD_DIM 64
#define DIM_FF  4096
#define BATCH   4
#define TC      1024
#define TP      1024
#define TK      2048
#define NROWS   (BATCH * TC)    // 4096
#define EPSF    1e-5f

// ---------------------------------------------------------------------------
// Scratch (device globals; no allocations allowed)
// ---------------------------------------------------------------------------
__device__ float          g_qkv  [(size_t)NROWS * 3 * D_MODEL];
__device__ float          g_x1   [(size_t)NROWS * D_MODEL];
__device__ __nv_bfloat16  g_h_hi [(size_t)NROWS * D_MODEL];
__device__ __nv_bfloat16  g_h_lo [(size_t)NROWS * D_MODEL];
__device__ __nv_bfloat16  g_o_hi [(size_t)NROWS * D_MODEL];
__device__ __nv_bfloat16  g_o_lo [(size_t)NROWS * D_MODEL];
__device__ __nv_bfloat16  g_h2_hi[(size_t)NROWS * D_MODEL];
__device__ __nv_bfloat16  g_h2_lo[(size_t)NROWS * D_MODEL];
__device__ __nv_bfloat16  g_ff_hi[(size_t)NROWS * DIM_FF];
__device__ __nv_bfloat16  g_ff_lo[(size_t)NROWS * DIM_FF];
// bf16 split K/V caches for tensor-core attention
__device__ __nv_bfloat16  g_Kbh[(size_t)BATCH * NHEAD * TK * HEAD_DIM];
__device__ __nv_bfloat16  g_Kbl[(size_t)BATCH * NHEAD * TK * HEAD_DIM];
__device__ __nv_bfloat16  g_Vbh[(size_t)BATCH * NHEAD * TK * HEAD_DIM];
__device__ __nv_bfloat16  g_Vbl[(size_t)BATCH * NHEAD * TK * HEAD_DIM];
// transposed-split weights [N,K]
__device__ __nv_bfloat16  g_wqkvT_hi[(size_t)3 * D_MODEL * D_MODEL];
__device__ __nv_bfloat16  g_wqkvT_lo[(size_t)3 * D_MODEL * D_MODEL];
__device__ __nv_bfloat16  g_woT_hi  [(size_t)D_MODEL * D_MODEL];
__device__ __nv_bfloat16  g_woT_lo  [(size_t)D_MODEL * D_MODEL];
__device__ __nv_bfloat16  g_w1T_hi  [(size_t)DIM_FF * D_MODEL];
__device__ __nv_bfloat16  g_w1T_lo  [(size_t)DIM_FF * D_MODEL];
__device__ __nv_bfloat16  g_w2T_hi  [(size_t)D_MODEL * DIM_FF];
__device__ __nv_bfloat16  g_w2T_lo  [(size_t)D_MODEL * DIM_FF];

// ---------------------------------------------------------------------------
// Helpers
// ---------------------------------------------------------------------------
__device__ __forceinline__ uint32_t s2u(const void* p) {
    uint32_t a;
    asm("{ .reg .u64 t; cvta.to.shared.u64 t, %1; cvt.u32.u64 %0, t; }" : "=r"(a) : "l"(p));
    return a;
}
__device__ __forceinline__ void cp16(uint32_t dst, const void* src) {
    asm volatile("cp.async.cg.shared.global [%0], [%1], 16;" :: "r"(dst), "l"(src));
}
#define CP_COMMIT() asm volatile("cp.async.commit_group;" ::: "memory")
#define CP_WAIT(n)  asm volatile("cp.async.wait_group %0;" :: "n"(n) : "memory")

__device__ __forceinline__ void ldsm4(uint32_t* r, uint32_t addr) {
    asm volatile("ldmatrix.sync.aligned.m8n8.x4.shared.b16 {%0,%1,%2,%3}, [%4];"
                 : "=r"(r[0]), "=r"(r[1]), "=r"(r[2]), "=r"(r[3]) : "r"(addr));
}
__device__ __forceinline__ void ldsm2(uint32_t* r, uint32_t addr) {
    asm volatile("ldmatrix.sync.aligned.m8n8.x2.shared.b16 {%0,%1}, [%2];"
                 : "=r"(r[0]), "=r"(r[1]) : "r"(addr));
}
__device__ __forceinline__ void ldsm2t(uint32_t* r, uint32_t addr) {
    asm volatile("ldmatrix.sync.aligned.m8n8.x2.trans.shared.b16 {%0,%1}, [%2];"
                 : "=r"(r[0]), "=r"(r[1]) : "r"(addr));
}
__device__ __forceinline__ void mma16816(float* d, const uint32_t* a, const uint32_t* b) {
    asm volatile(
        "mma.sync.aligned.m16n8k16.row.col.f32.bf16.bf16.f32 "
        "{%0,%1,%2,%3}, {%4,%5,%6,%7}, {%8,%9}, {%0,%1,%2,%3};"
        : "+f"(d[0]), "+f"(d[1]), "+f"(d[2]), "+f"(d[3])
        : "r"(a[0]), "r"(a[1]), "r"(a[2]), "r"(a[3]), "r"(b[0]), "r"(b[1]));
}
// pack two fp32 into bf16x2 hi and residual-lo
__device__ __forceinline__ void packsplit(float v0, float v1, uint32_t& hi, uint32_t& lo) {
    __nv_bfloat16 h0 = __float2bfloat16(v0), h1 = __float2bfloat16(v1);
    __nv_bfloat16 l0 = __float2bfloat16(v0 - __bfloat162float(h0));
    __nv_bfloat16 l1 = __float2bfloat16(v1 - __bfloat162float(h1));
    __nv_bfloat162 H(h0, h1), L(l0, l1);
    hi = *(uint32_t*)&H; lo = *(uint32_t*)&L;
}

// ---------------------------------------------------------------------------
// LayerNorm -> split bf16 hi/lo
// ---------------------------------------------------------------------------
__global__ void ln_split_kernel(const float* __restrict__ x, const float* __restrict__ g,
                                const float* __restrict__ be,
                                __nv_bfloat16* __restrict__ hi, __nv_bfloat16* __restrict__ lo) {
    __shared__ float red[16];
    __shared__ float s_mu, s_rstd;
    const int row = blockIdx.x;
    const int tid = threadIdx.x;
    const float4 v = ((const float4*)(x + (size_t)row * D_MODEL))[tid];
    float s  = v.x + v.y + v.z + v.w;
    float sq = fmaf(v.x, v.x, fmaf(v.y, v.y, fmaf(v.z, v.z, v.w * v.w)));
#pragma unroll
    for (int o = 16; o; o >>= 1) {
        s  += __shfl_xor_sync(0xFFFFFFFFu, s, o);
        sq += __shfl_xor_sync(0xFFFFFFFFu, sq, o);
    }
    const int w = tid >> 5, lane = tid & 31;
    if (lane == 0) { red[w] = s; red[w + 8] = sq; }
    __syncthreads();
    if (tid == 0) {
        float S = 0.f, Q = 0.f;
#pragma unroll
        for (int i = 0; i < 8; i++) { S += red[i]; Q += red[i + 8]; }
        float mu  = S * (1.f / D_MODEL);
        float var = Q * (1.f / D_MODEL) - mu * mu;
        s_mu = mu; s_rstd = rsqrtf(var + EPSF);
    }
    __syncthreads();
    const float mu = s_mu, rstd = s_rstd;
    const float4 gv = ((const float4*)g)[tid];
    const float4 bv = ((const float4*)be)[tid];
    float o4[4];
    o4[0] = (v.x - mu) * rstd * gv.x + bv.x;
    o4[1] = (v.y - mu) * rstd * gv.y + bv.y;
    o4[2] = (v.z - mu) * rstd * gv.z + bv.z;
    o4[3] = (v.w - mu) * rstd * gv.w + bv.w;
    __nv_bfloat162* hp = (__nv_bfloat162*)(hi + (size_t)row * D_MODEL) + tid * 2;
    __nv_bfloat162* lp = (__nv_bfloat162*)(lo + (size_t)row * D_MODEL) + tid * 2;
#pragma unroll
    for (int j = 0; j < 2; j++) {
        uint32_t h, l;
        packsplit(o4[2 * j], o4[2 * j + 1], h, l);
        hp[j] = *(__nv_bfloat162*)&h;
        lp[j] = *(__nv_bfloat162*)&l;
    }
}

// ---------------------------------------------------------------------------
// Weight transpose + split
// ---------------------------------------------------------------------------
__global__ void transpose_split(const float* __restrict__ W,
                                __nv_bfloat16* __restrict__ hi, __nv_bfloat16* __restrict__ lo,
                                int K, int N) {
    __shared__ float t[32][33];
    const int k0 = blockIdx.y * 32, n0 = blockIdx.x * 32;
    const int tx = threadIdx.x & 31, ty = threadIdx.x >> 5;
#pragma unroll
    for (int i = 0; i < 32; i += 8)
        t[ty + i][tx] = W[(size_t)(k0 + ty + i) * N + n0 + tx];
    __syncthreads();
#pragma unroll
    for (int i = 0; i < 32; i += 8) {
        float v = t[tx][ty + i];
        __nv_bfloat16 h = __float2bfloat16(v);
        __nv_bfloat16 l = __float2bfloat16(v - __bfloat162float(h));
        hi[(size_t)(n0 + ty + i) * K + k0 + tx] = h;
        lo[(size_t)(n0 + ty + i) * K + k0 + tx] = l;
    }
}

// ---------------------------------------------------------------------------
// mma.sync bf16 split GEMM, 3-stage cp.async pipeline
// ---------------------------------------------------------------------------
#define TPAD_B   80
#define TILE_B   (128 * TPAD_B)
#define BUF_B    (4 * TILE_B)            // 40960
#define GM_SMEM  (3 * BUF_B)             // 122880

template<int EPI>
__global__ __launch_bounds__(256, 1)
void gemm_mma(const __nv_bfloat16* __restrict__ Ahi, const __nv_bfloat16* __restrict__ Alo,
              const __nv_bfloat16* __restrict__ Bhi, const __nv_bfloat16* __restrict__ Blo,
              const float* __restrict__ bias, const float* __restrict__ Res,
              float* __restrict__ C, __nv_bfloat16* __restrict__ Chi, __nv_bfloat16* __restrict__ Clo,
              int N, int K) {
    extern __shared__ char smc[];
    const uint32_t sb = s2u(smc);
    const int tid  = threadIdx.x;
    const int lane = tid & 31;
    const int wid  = tid >> 5;
    const int wm   = wid >> 2;
    const int wn   = wid & 3;
    const int bm = blockIdx.y * 128;
    const int bn = blockIdx.x * 128;

    const __nv_bfloat16* src0 = Ahi + (size_t)bm * K;
    const __nv_bfloat16* src1 = Alo + (size_t)bm * K;
    const __nv_bfloat16* src2 = Bhi + (size_t)bn * K;
    const __nv_bfloat16* src3 = Blo + (size_t)bn * K;

    const int r0 = tid >> 2,         c0 = tid & 3;
    const int r1 = (tid + 256) >> 2, c1 = tid & 3;

#define PREFETCH(kb, buf)                                                          \
    do {                                                                           \
        const uint32_t db = sb + (buf) * BUF_B;                                    \
        const int ko = (kb) * 32;                                                  \
        cp16(db + 0*TILE_B + r0*TPAD_B + c0*16, (const char*)(src0 + (size_t)r0*K + ko) + c0*16); \
        cp16(db + 0*TILE_B + r1*TPAD_B + c1*16, (const char*)(src0 + (size_t)r1*K + ko) + c1*16); \
        cp16(db + 1*TILE_B + r0*TPAD_B + c0*16, (const char*)(src1 + (size_t)r0*K + ko) + c0*16); \
        cp16(db + 1*TILE_B + r1*TPAD_B + c1*16, (const char*)(src1 + (size_t)r1*K + ko) + c1*16); \
        cp16(db + 2*TILE_B + r0*TPAD_B + c0*16, (const char*)(src2 + (size_t)r0*K + ko) + c0*16); \
        cp16(db + 2*TILE_B + r1*TPAD_B + c1*16, (const char*)(src2 + (size_t)r1*K + ko) + c1*16); \
        cp16(db + 3*TILE_B + r0*TPAD_B + c0*16, (const char*)(src3 + (size_t)r0*K + ko) + c0*16); \
        cp16(db + 3*TILE_B + r1*TPAD_B + c1*16, (const char*)(src3 + (size_t)r1*K + ko) + c1*16); \
        CP_COMMIT();                                                               \
    } while (0)

    float acc[4][4][4];
#pragma unroll
    for (int m = 0; m < 4; m++)
#pragma unroll
        for (int n = 0; n < 4; n++)
#pragma unroll
            for (int i = 0; i < 4; i++) acc[m][n][i] = 0.f;

    const int NKB = K >> 5;
    PREFETCH(0, 0);
    PREFETCH(1, 1);

    int buf = 0, nbuf = 2;
    for (int kb = 0; kb < NKB; kb++) {
        if (kb + 2 < NKB) { PREFETCH(kb + 2, nbuf); CP_WAIT(2); }
        else if (kb + 1 < NKB) CP_WAIT(1);
        else CP_WAIT(0);
        __syncthreads();

        const uint32_t b  = sb + buf * BUF_B;
        const uint32_t Ah = b, Al = b + TILE_B, Bh = b + 2 * TILE_B, Bl = b + 3 * TILE_B;
#pragma unroll
        for (int ks = 0; ks < 2; ks++) {
            uint32_t ah[4][4], al[4][4], bh[4][2], bl[4][2];
            const uint32_t aoff = (uint32_t)(wm * 64 + (lane & 15)) * TPAD_B + ks * 32 + (lane >> 4) * 16;
            const uint32_t boff = (uint32_t)(wn * 32 + (lane & 7)) * TPAD_B + ks * 32 + ((lane >> 3) & 1) * 16;
#pragma unroll
            for (int m = 0; m < 4; m++) {
                ldsm4(ah[m], Ah + aoff + m * 16 * TPAD_B);
                ldsm4(al[m], Al + aoff + m * 16 * TPAD_B);
            }
#pragma unroll
            for (int n = 0; n < 4; n++) {
                ldsm2(bh[n], Bh + boff + n * 8 * TPAD_B);
                ldsm2(bl[n], Bl + boff + n * 8 * TPAD_B);
            }
#pragma unroll
            for (int m = 0; m < 4; m++)
#pragma unroll
                for (int n = 0; n < 4; n++) {
                    mma16816(acc[m][n], ah[m], bh[n]);
                    mma16816(acc[m][n], al[m], bh[n]);
                    mma16816(acc[m][n], ah[m], bl[n]);
                }
        }
        __syncthreads();
        buf = (buf + 1) % 3;
        nbuf = (nbuf + 1) % 3;
    }

#pragma unroll
    for (int m = 0; m < 4; m++)
#pragma unroll
        for (int n = 0; n < 4; n++) {
            const int col  = bn + wn * 32 + n * 8 + 2 * (lane & 3);
            const float b0 = bias[col], b1 = bias[col + 1];
#pragma unroll
            for (int half = 0; half < 2; half++) {
                const int row = bm + wm * 64 + m * 16 + (lane >> 2) + half * 8;
                float v0 = acc[m][n][2 * half]     + b0;
                float v1 = acc[m][n][2 * half + 1] + b1;
                if (EPI == 2) {
                    v0 = 0.5f * v0 * (1.f + erff(v0 * 0.70710678118654752f));
                    v1 = 0.5f * v1 * (1.f + erff(v1 * 0.70710678118654752f));
                    uint32_t h, l;
                    packsplit(v0, v1, h, l);
                    *(__nv_bfloat162*)(Chi + (size_t)row * N + col) = *(__nv_bfloat162*)&h;
                    *(__nv_bfloat162*)(Clo + (size_t)row * N + col) = *(__nv_bfloat162*)&l;
                } else {
                    if (EPI == 1) {
                        const float2 rv = *(const float2*)(Res + (size_t)row * N + col);
                        v0 += rv.x; v1 += rv.y;
                    }
                    float2 o2; o2.x = v0; o2.y = v1;
                    *(float2*)(C + (size_t)row * N + col) = o2;
                }
            }
        }
#undef PREFETCH
}

// ---------------------------------------------------------------------------
// Build K/V caches: fp32 to d_out, plus bf16 hi/lo splits for attention
// ---------------------------------------------------------------------------
__global__ void build_kv(const float* __restrict__ Kp, const float* __restrict__ Vp,
                         const float* __restrict__ qkv,
                         float* __restrict__ outK, float* __restrict__ outV) {
    const size_t PER = (size_t)BATCH * NHEAD * TK * HEAD_DIM / 4;
    size_t i = (size_t)blockIdx.x * blockDim.x + threadIdx.x;
    if (i >= 2 * PER) return;
    const int which = i >= PER;
    const size_t j = which ? (i - PER) : i;
    const size_t rowi = j >> 4;
    const int d4 = (int)(j & 15);
    const size_t bh = rowi >> 11;
    const int t = (int)(rowi & (TK - 1));
    float4 v;
    if (t < TP) {
        const float* src = (which ? Vp : Kp) + ((bh * TP + t) << 6) + (d4 << 2);
        v = *(const float4*)src;
    } else {
        const int h = (int)(bh & (NHEAD - 1));
        const size_t b = bh >> 4;
        const float* src = qkv + (b * TC + (t - TP)) * (size_t)(3 * D_MODEL)
                               + (which ? 2 * D_MODEL : D_MODEL) + h * HEAD_DIM + (d4 << 2);
        v = *(const float4*)src;
    }
    ((float4*)(which ? outV : outK))[rowi * 16 + d4] = v;
    // bf16 splits
    uint32_t h01, l01, h23, l23;
    packsplit(v.x, v.y, h01, l01);
    packsplit(v.z, v.w, h23, l23);
    const size_t eb = rowi * 64 + (size_t)d4 * 4;
    __nv_bfloat162* Hp = (__nv_bfloat162*)((which ? g_Vbh : g_Kbh) + eb);
    __nv_bfloat162* Lp = (__nv_bfloat162*)((which ? g_Vbl : g_Kbl) + eb);
    Hp[0] = *(__nv_bfloat162*)&h01; Hp[1] = *(__nv_bfloat162*)&h23;
    Lp[0] = *(__nv_bfloat162*)&l01; Lp[1] = *(__nv_bfloat162*)&l23;
}

// ---------------------------------------------------------------------------
// Tensor-core flash attention: 64 q-rows per CTA, 4 warps (m16 each).
// S = Q K^T (3-term split), softmax in accum layout, O += P V (3-term split,
// P packed in registers, V via ldmatrix.trans).
// ---------------------------------------------------------------------------
#define QPAD     72                       // bf16 elems per smem row (144 B)
#define AT_TILE  (64 * QPAD)              // elems; bytes = 9216
#define AT_TILEB 9216
#define AT_SMEM  (18432 + 2 * 4 * AT_TILEB)   // Qh,Ql + 2 buf x (Kh,Kl,Vh,Vl) = 92160

__global__ __launch_bounds__(128)
void attn_mma(const float* __restrict__ qkv, const int* __restrict__ pos_ptr) {
    extern __shared__ char sma[];
    const uint32_t sbase = s2u(sma);
    const int tid = threadIdx.x, lane = tid & 31, w = tid >> 5;
    const int qb = blockIdx.x, bh = blockIdx.y;
    const int b = bh >> 4, h = bh & 15;
    const int q0 = qb * 64;
    const int pos = *pos_ptr;
    const size_t kvbase = (size_t)bh * TK * HEAD_DIM;

#define AT_PRE(kb, bufi)                                                            \
    do {                                                                            \
        const size_t srcb = kvbase + (size_t)(kb) * 64 * 64;                        \
        const uint32_t db = sbase + 18432 + (bufi) * (4 * AT_TILEB);                \
        _Pragma("unroll")                                                           \
        for (int t_ = 0; t_ < 4; t_++) {                                            \
            const int i_ = tid + t_ * 128;                                          \
            const int row_ = i_ >> 3; const int ch_ = (i_ & 7) * 16;                \
            const uint32_t doff = (uint32_t)row_ * 144 + ch_;                       \
            const size_t soff = srcb + (size_t)row_ * 64;                           \
            cp16(db + 0 * AT_TILEB + doff, (const char*)(g_Kbh + soff) + ch_);      \
            cp16(db + 1 * AT_TILEB + doff, (const char*)(g_Kbl + soff) + ch_);      \
            cp16(db + 2 * AT_TILEB + doff, (const char*)(g_Vbh + soff) + ch_);      \
            cp16(db + 3 * AT_TILEB + doff, (const char*)(g_Vbl + soff) + ch_);      \
        }                                                                           \
        CP_COMMIT();                                                                \
    } while (0)

    AT_PRE(0, 0);

    // load Q tile (64x64 fp32) -> split bf16 smem
    {
        const int qr = tid >> 1, dh = (tid & 1) * 32;
        const float* src = qkv + (size_t)(b * TC + q0 + qr) * (3 * D_MODEL) + h * HEAD_DIM + dh;
        __nv_bfloat162* hp = (__nv_bfloat162*)(sma + qr * 144 + dh * 2);
        __nv_bfloat162* lp = (__nv_bfloat162*)(sma + AT_TILEB + qr * 144 + dh * 2);
#pragma unroll
        for (int i = 0; i < 32; i += 4) {
            float4 v = *(const float4*)(src + i);
            uint32_t h01, l01, h23, l23;
            packsplit(v.x, v.y, h01, l01);
            packsplit(v.z, v.w, h23, l23);
            hp[i / 2]     = *(__nv_bfloat162*)&h01;
            hp[i / 2 + 1] = *(__nv_bfloat162*)&h23;
            lp[i / 2]     = *(__nv_bfloat162*)&l01;
            lp[i / 2 + 1] = *(__nv_bfloat162*)&l23;
        }
    }
    __syncthreads();

    float oacc[8][4];
#pragma unroll
    for (int nb = 0; nb < 8; nb++)
#pragma unroll
        for (int i = 0; i < 4; i++) oacc[nb][i] = 0.f;
    float m0 = -1e30f, m1 = -1e30f, l0 = 0.f, l1 = 0.f;

    const int r0 = lane >> 2;                     // rows r0, r0+8 of warp tile
    const int lim0 = pos + q0 + w * 16 + r0;      // last allowed key, row r0
    const int lim1 = lim0 + 8;
    const int warp_lim = pos + q0 + w * 16;       // min limit in this warp
    const int nkb = (pos + q0 + 127) >> 6;

    const uint32_t arow = (uint32_t)(w * 16 + (lane & 15)) * 144 + (lane >> 4) * 16;
    const uint32_t brow = (uint32_t)(lane & 7) * 144 + ((lane >> 3) & 1) * 16;

    for (int kb = 0; kb < nkb; kb++) {
        if (kb + 1 < nkb) { AT_PRE(kb + 1, (kb + 1) & 1); CP_WAIT(1); }
        else CP_WAIT(0);
        __syncthreads();

        const uint32_t bb  = sbase + 18432 + (kb & 1) * (4 * AT_TILEB);
        const uint32_t Kh = bb, Kl = bb + AT_TILEB, Vh = bb + 2 * AT_TILEB, Vl = bb + 3 * AT_TILEB;

        // ---- S = Q K^T ----
        float sacc[8][4];
#pragma unroll
        for (int nb = 0; nb < 8; nb++)
#pragma unroll
            for (int i = 0; i < 4; i++) sacc[nb][i] = 0.f;
#pragma unroll
        for (int ks = 0; ks < 4; ks++) {
            uint32_t ah[4], al[4];
            ldsm4(ah, sbase + arow + ks * 32);
            ldsm4(al, sbase + AT_TILEB + arow + ks * 32);
#pragma unroll
            for (int nb = 0; nb < 8; nb++) {
                uint32_t kh2[2], kl2[2];
                ldsm2(kh2, Kh + brow + nb * (8 * 144) + ks * 32);
                ldsm2(kl2, Kl + brow + nb * (8 * 144) + ks * 32);
                mma16816(sacc[nb], ah, kh2);
                mma16816(sacc[nb], al, kh2);
                mma16816(sacc[nb], ah, kl2);
            }
        }

        // ---- scale + mask ----
        const int kstart = kb * 64;
        if (kstart + 63 <= warp_lim) {
#pragma unroll
            for (int nb = 0; nb < 8; nb++)
#pragma unroll
                for (int i = 0; i < 4; i++) sacc[nb][i] *= 0.125f;
        } else {
#pragma unroll
            for (int nb = 0; nb < 8; nb++) {
                const int tok = kstart + nb * 8 + 2 * (lane & 3);
                sacc[nb][0] = (tok     <= lim0) ? sacc[nb][0] * 0.125f : -1e30f;
                sacc[nb][1] = (tok + 1 <= lim0) ? sacc[nb][1] * 0.125f : -1e30f;
                sacc[nb][2] = (tok     <= lim1) ? sacc[nb][2] * 0.125f : -1e30f;
                sacc[nb][3] = (tok + 1 <= lim1) ? sacc[nb][3] * 0.125f : -1e30f;
            }
        }

        // ---- online softmax ----
        float mx0 = -1e30f, mx1 = -1e30f;
#pragma unroll
        for (int nb = 0; nb < 8; nb++) {
            mx0 = fmaxf(mx0, fmaxf(sacc[nb][0], sacc[nb][1]));
            mx1 = fmaxf(mx1, fmaxf(sacc[nb][2], sacc[nb][3]));
        }
        mx0 = fmaxf(mx0, __shfl_xor_sync(0xFFFFFFFFu, mx0, 1));
        mx0 = fmaxf(mx0, __shfl_xor_sync(0xFFFFFFFFu, mx0, 2));
        mx1 = fmaxf(mx1, __shfl_xor_sync(0xFFFFFFFFu, mx1, 1));
        mx1 = fmaxf(mx1, __shfl_xor_sync(0xFFFFFFFFu, mx1, 2));
        const float mn0 = fmaxf(m0, mx0), mn1 = fmaxf(m1, mx1);
        const float al0 = __expf(m0 - mn0), al1 = __expf(m1 - mn1);
        m0 = mn0; m1 = mn1;
        float ls0 = 0.f, ls1 = 0.f;
#pragma unroll
        for (int nb = 0; nb < 8; nb++) {
            sacc[nb][0] = __expf(sacc[nb][0] - mn0);
            sacc[nb][1] = __expf(sacc[nb][1] - mn0);
            sacc[nb][2] = __expf(sacc[nb][2] - mn1);
            sacc[nb][3] = __expf(sacc[nb][3] - mn1);
            ls0 += sacc[nb][0] + sacc[nb][1];
            ls1 += sacc[nb][2] + sacc[nb][3];
        }
        ls0 += __shfl_xor_sync(0xFFFFFFFFu, ls0, 1);
        ls0 += __shfl_xor_sync(0xFFFFFFFFu, ls0, 2);
        ls1 += __shfl_xor_sync(0xFFFFFFFFu, ls1, 1);
        ls1 += __shfl_xor_sync(0xFFFFFFFFu, ls1, 2);
        l0 = l0 * al0 + ls0;
        l1 = l1 * al1 + ls1;
#pragma unroll
        for (int nb = 0; nb < 8; nb++) {
            oacc[nb][0] *= al0; oacc[nb][1] *= al0;
            oacc[nb][2] *= al1; oacc[nb][3] *= al1;
        }

        // ---- O += P V ----
#pragma unroll
        for (int ks = 0; ks < 4; ks++) {
            uint32_t phi[4], plo[4];
            packsplit(sacc[2 * ks][0],     sacc[2 * ks][1],     phi[0], plo[0]);
            packsplit(sacc[2 * ks][2],     sacc[2 * ks][3],     phi[1], plo[1]);
            packsplit(sacc[2 * ks + 1][0], sacc[2 * ks + 1][1], phi[2], plo[2]);
            packsplit(sacc[2 * ks + 1][2], sacc[2 * ks + 1][3], phi[3], plo[3]);
            const uint32_t voff = (uint32_t)(ks * 16 + (lane & 15)) * 144;
#pragma unroll
            for (int nb = 0; nb < 8; nb++) {
                uint32_t vh2[2], vl2[2];
                ldsm2t(vh2, Vh + voff + nb * 16);
                ldsm2t(vl2, Vl + voff + nb * 16);
                mma16816(oacc[nb], phi, vh2);
                mma16816(oacc[nb], plo, vh2);
                mma16816(oacc[nb], phi, vl2);
            }
        }
        __syncthreads();
    }

    // ---- epilogue: normalize, split, store ----
    const float inv0 = 1.f / l0, inv1 = 1.f / l1;
    const int grow0 = b * TC + q0 + w * 16 + r0;
#pragma unroll
    for (int nb = 0; nb < 8; nb++) {
        const int col = h * HEAD_DIM + nb * 8 + 2 * (lane & 3);
        uint32_t hh, ll;
        packsplit(oacc[nb][0] * inv0, oacc[nb][1] * inv0, hh, ll);
        *(__nv_bfloat162*)(g_o_hi + (size_t)grow0 * D_MODEL + col) = *(__nv_bfloat162*)&hh;
        *(__nv_bfloat162*)(g_o_lo + (size_t)grow0 * D_MODEL + col) = *(__nv_bfloat162*)&ll;
        packsplit(oacc[nb][2] * inv1, oacc[nb][3] * inv1, hh, ll);
        *(__nv_bfloat162*)(g_o_hi + (size_t)(grow0 + 8) * D_MODEL + col) = *(__nv_bfloat162*)&hh;
        *(__nv_bfloat162*)(g_o_lo + (size_t)(grow0 + 8) * D_MODEL + col) = *(__nv_bfloat162*)&ll;
    }
#undef AT_PRE
}

// ---------------------------------------------------------------------------
// Launch
// ---------------------------------------------------------------------------
extern "C" void kernel_launch(void* const* d_in, const int* in_sizes, int n_in,
                              void* d_out, int out_size) {
    const float* x    = (const float*)d_in[0];
    const float* Kp   = (const float*)d_in[1];
    const float* Vp   = (const float*)d_in[2];
    const int*   posp = (const int*)  d_in[3];
    const float* wqkv = (const float*)d_in[4];
    const float* bqkv = (const float*)d_in[5];
    const float* wo   = (const float*)d_in[6];
    const float* bo   = (const float*)d_in[7];
    const float* g1   = (const float*)d_in[8];
    const float* be1  = (const float*)d_in[9];
    const float* g2   = (const float*)d_in[10];
    const float* be2  = (const float*)d_in[11];
    const float* w1   = (const float*)d_in[12];
    const float* bf1  = (const float*)d_in[13];
    const float* w2   = (const float*)d_in[14];
    const float* bf2  = (const float*)d_in[15];

    float* out_x = (float*)d_out;
    float* out_K = out_x + (size_t)BATCH * TC * D_MODEL;
    float* out_V = out_K + (size_t)BATCH * NHEAD * TK * HEAD_DIM;

    void* p;
    cudaGetSymbolAddress(&p, g_qkv);      float* qkv = (float*)p;
    cudaGetSymbolAddress(&p, g_x1);       float* x1  = (float*)p;
    cudaGetSymbolAddress(&p, g_h_hi);     __nv_bfloat16* hhi = (__nv_bfloat16*)p;
    cudaGetSymbolAddress(&p, g_h_lo);     __nv_bfloat16* hlo = (__nv_bfloat16*)p;
    cudaGetSymbolAddress(&p, g_o_hi);     __nv_bfloat16* ohi = (__nv_bfloat16*)p;
    cudaGetSymbolAddress(&p, g_o_lo);     __nv_bfloat16* olo = (__nv_bfloat16*)p;
    cudaGetSymbolAddress(&p, g_h2_hi);    __nv_bfloat16* h2hi = (__nv_bfloat16*)p;
    cudaGetSymbolAddress(&p, g_h2_lo);    __nv_bfloat16* h2lo = (__nv_bfloat16*)p;
    cudaGetSymbolAddress(&p, g_ff_hi);    __nv_bfloat16* ffhi = (__nv_bfloat16*)p;
    cudaGetSymbolAddress(&p, g_ff_lo);    __nv_bfloat16* fflo = (__nv_bfloat16*)p;
    cudaGetSymbolAddress(&p, g_wqkvT_hi); __nv_bfloat16* wqkvThi = (__nv_bfloat16*)p;
    cudaGetSymbolAddress(&p, g_wqkvT_lo); __nv_bfloat16* wqkvTlo = (__nv_bfloat16*)p;
    cudaGetSymbolAddress(&p, g_woT_hi);   __nv_bfloat16* woThi = (__nv_bfloat16*)p;
    cudaGetSymbolAddress(&p, g_woT_lo);   __nv_bfloat16* woTlo = (__nv_bfloat16*)p;
    cudaGetSymbolAddress(&p, g_w1T_hi);   __nv_bfloat16* w1Thi = (__nv_bfloat16*)p;
    cudaGetSymbolAddress(&p, g_w1T_lo);   __nv_bfloat16* w1Tlo = (__nv_bfloat16*)p;
    cudaGetSymbolAddress(&p, g_w2T_hi);   __nv_bfloat16* w2Thi = (__nv_bfloat16*)p;
    cudaGetSymbolAddress(&p, g_w2T_lo);   __nv_bfloat16* w2Tlo = (__nv_bfloat16*)p;

    cudaFuncSetAttribute(attn_mma, cudaFuncAttributeMaxDynamicSharedMemorySize, AT_SMEM);
    cudaFuncSetAttribute(gemm_mma<0>, cudaFuncAttributeMaxDynamicSharedMemorySize, GM_SMEM);
    cudaFuncSetAttribute(gemm_mma<1>, cudaFuncAttributeMaxDynamicSharedMemorySize, GM_SMEM);
    cudaFuncSetAttribute(gemm_mma<2>, cudaFuncAttributeMaxDynamicSharedMemorySize, GM_SMEM);

    // 0) weight transpose + split
    transpose_split<<<dim3(3 * D_MODEL / 32, D_MODEL / 32), 256>>>(wqkv, wqkvThi, wqkvTlo, D_MODEL, 3 * D_MODEL);
    transpose_split<<<dim3(D_MODEL / 32, D_MODEL / 32), 256>>>(wo, woThi, woTlo, D_MODEL, D_MODEL);
    transpose_split<<<dim3(DIM_FF / 32, D_MODEL / 32), 256>>>(w1, w1Thi, w1Tlo, D_MODEL, DIM_FF);
    transpose_split<<<dim3(D_MODEL / 32, DIM_FF / 32), 256>>>(w2, w2Thi, w2Tlo, DIM_FF, D_MODEL);
    // 1) LN1 -> split
    ln_split_kernel<<<NROWS, 256>>>(x, g1, be1, hhi, hlo);
    // 2) QKV GEMM
    gemm_mma<0><<<dim3(3 * D_MODEL / 128, NROWS / 128), 256, GM_SMEM>>>(
        hhi, hlo, wqkvThi, wqkvTlo, bqkv, nullptr, qkv, nullptr, nullptr, 3 * D_MODEL, D_MODEL);
    // 3) KV cache assembly (fp32 out + bf16 splits)
    build_kv<<<16384, 256>>>(Kp, Vp, qkv, out_K, out_V);
    // 4) Tensor-core flash attention -> o hi/lo
    attn_mma<<<dim3(TC / 64, BATCH * NHEAD), 128, AT_SMEM>>>(qkv, posp);
    // 5) O-proj + residual -> x1
    gemm_mma<1><<<dim3(D_MODEL / 128, NROWS / 128), 256, GM_SMEM>>>(
        ohi, olo, woThi, woTlo, bo, x, x1, nullptr, nullptr, D_MODEL, D_MODEL);
    // 6) LN2 -> split
    ln_split_kernel<<<NROWS, 256>>>(x1, g2, be2, h2hi, h2lo);
    // 7) FFN1 + GELU -> ff hi/lo
    gemm_mma<2><<<dim3(DIM_FF / 128, NROWS / 128), 256, GM_SMEM>>>(
        h2hi, h2lo, w1Thi, w1Tlo, bf1, nullptr, nullptr, ffhi, fflo, DIM_FF, D_MODEL);
    // 8) FFN2 + residual -> out_x
    gemm_mma<1><<<dim3(D_MODEL / 128, NROWS / 128), 256, GM_SMEM>>>(
        ffhi, fflo, w2Thi, w2Tlo, bf2, x1, out_x, nullptr, nullptr, D_MODEL, DIM_FF);
}

// round 7
// speedup vs baseline: 4.2098x; 1.0649x over previous
#include <cuda_runtime.h>
#include <cuda_bf16.h>
#include <math.h>
#include <stdint.h>

// ---------------------------------------------------------------------------
// Problem constants
// ---------------------------------------------------------------------------
#define D_MODEL 1024
#define NHEAD   16
#define HEAD_DIM 64
#define DIM_FF  4096
#define BATCH   4
#define TC      1024
#define TP      1024
#define TK      2048
#define NROWS   (BATCH * TC)    // 4096
#define EPSF    1e-5f

// ---------------------------------------------------------------------------
// Scratch (device globals; no allocations allowed)
// ---------------------------------------------------------------------------
__device__ float          g_qkv  [(size_t)NROWS * 3 * D_MODEL];   // K,V thirds used
__device__ float          g_x1   [(size_t)NROWS * D_MODEL];
__device__ __nv_bfloat16  g_h_hi [(size_t)NROWS * D_MODEL];
__device__ __nv_bfloat16  g_h_lo [(size_t)NROWS * D_MODEL];
__device__ __nv_bfloat16  g_q_hi [(size_t)NROWS * D_MODEL];
__device__ __nv_bfloat16  g_q_lo [(size_t)NROWS * D_MODEL];
__device__ __nv_bfloat16  g_o_hi [(size_t)NROWS * D_MODEL];
__device__ __nv_bfloat16  g_o_lo [(size_t)NROWS * D_MODEL];
__device__ __nv_bfloat16  g_h2_hi[(size_t)NROWS * D_MODEL];
__device__ __nv_bfloat16  g_h2_lo[(size_t)NROWS * D_MODEL];
__device__ __nv_bfloat16  g_ff_hi[(size_t)NROWS * DIM_FF];
__device__ __nv_bfloat16  g_ff_lo[(size_t)NROWS * DIM_FF];
// bf16 split K/V caches for tensor-core attention
__device__ __nv_bfloat16  g_Kbh[(size_t)BATCH * NHEAD * TK * HEAD_DIM];
__device__ __nv_bfloat16  g_Kbl[(size_t)BATCH * NHEAD * TK * HEAD_DIM];
__device__ __nv_bfloat16  g_Vbh[(size_t)BATCH * NHEAD * TK * HEAD_DIM];
__device__ __nv_bfloat16  g_Vbl[(size_t)BATCH * NHEAD * TK * HEAD_DIM];
// transposed-split weights [N,K]
__device__ __nv_bfloat16  g_wqkvT_hi[(size_t)3 * D_MODEL * D_MODEL];
__device__ __nv_bfloat16  g_wqkvT_lo[(size_t)3 * D_MODEL * D_MODEL];
__device__ __nv_bfloat16  g_woT_hi  [(size_t)D_MODEL * D_MODEL];
__device__ __nv_bfloat16  g_woT_lo  [(size_t)D_MODEL * D_MODEL];
__device__ __nv_bfloat16  g_w1T_hi  [(size_t)DIM_FF * D_MODEL];
__device__ __nv_bfloat16  g_w1T_lo  [(size_t)DIM_FF * D_MODEL];
__device__ __nv_bfloat16  g_w2T_hi  [(size_t)D_MODEL * DIM_FF];
__device__ __nv_bfloat16  g_w2T_lo  [(size_t)D_MODEL * DIM_FF];

// ---------------------------------------------------------------------------
// Helpers
// ---------------------------------------------------------------------------
__device__ __forceinline__ uint32_t s2u(const void* p) {
    uint32_t a;
    asm("{ .reg .u64 t; cvta.to.shared.u64 t, %1; cvt.u32.u64 %0, t; }" : "=r"(a) : "l"(p));
    return a;
}
__device__ __forceinline__ void cp16(uint32_t dst, const void* src) {
    asm volatile("cp.async.cg.shared.global [%0], [%1], 16;" :: "r"(dst), "l"(src));
}
#define CP_COMMIT() asm volatile("cp.async.commit_group;" ::: "memory")
#define CP_WAIT(n)  asm volatile("cp.async.wait_group %0;" :: "n"(n) : "memory")

__device__ __forceinline__ void ldsm4(uint32_t* r, uint32_t addr) {
    asm volatile("ldmatrix.sync.aligned.m8n8.x4.shared.b16 {%0,%1,%2,%3}, [%4];"
                 : "=r"(r[0]), "=r"(r[1]), "=r"(r[2]), "=r"(r[3]) : "r"(addr));
}
__device__ __forceinline__ void ldsm4t(uint32_t* r, uint32_t addr) {
    asm volatile("ldmatrix.sync.aligned.m8n8.x4.trans.shared.b16 {%0,%1,%2,%3}, [%4];"
                 : "=r"(r[0]), "=r"(r[1]), "=r"(r[2]), "=r"(r[3]) : "r"(addr));
}
__device__ __forceinline__ void mma16816(float* d, const uint32_t* a, const uint32_t* b) {
    asm volatile(
        "mma.sync.aligned.m16n8k16.row.col.f32.bf16.bf16.f32 "
        "{%0,%1,%2,%3}, {%4,%5,%6,%7}, {%8,%9}, {%0,%1,%2,%3};"
        : "+f"(d[0]), "+f"(d[1]), "+f"(d[2]), "+f"(d[3])
        : "r"(a[0]), "r"(a[1]), "r"(a[2]), "r"(a[3]), "r"(b[0]), "r"(b[1]));
}
__device__ __forceinline__ void packsplit(float v0, float v1, uint32_t& hi, uint32_t& lo) {
    __nv_bfloat16 h0 = __float2bfloat16(v0), h1 = __float2bfloat16(v1);
    __nv_bfloat16 l0 = __float2bfloat16(v0 - __bfloat162float(h0));
    __nv_bfloat16 l1 = __float2bfloat16(v1 - __bfloat162float(h1));
    __nv_bfloat162 H(h0, h1), L(l0, l1);
    hi = *(uint32_t*)&H; lo = *(uint32_t*)&L;
}

// ---------------------------------------------------------------------------
// LayerNorm -> split bf16 hi/lo
// ---------------------------------------------------------------------------
__global__ void ln_split_kernel(const float* __restrict__ x, const float* __restrict__ g,
                                const float* __restrict__ be,
                                __nv_bfloat16* __restrict__ hi, __nv_bfloat16* __restrict__ lo) {
    __shared__ float red[16];
    __shared__ float s_mu, s_rstd;
    const int row = blockIdx.x;
    const int tid = threadIdx.x;
    const float4 v = ((const float4*)(x + (size_t)row * D_MODEL))[tid];
    float s  = v.x + v.y + v.z + v.w;
    float sq = fmaf(v.x, v.x, fmaf(v.y, v.y, fmaf(v.z, v.z, v.w * v.w)));
#pragma unroll
    for (int o = 16; o; o >>= 1) {
        s  += __shfl_xor_sync(0xFFFFFFFFu, s, o);
        sq += __shfl_xor_sync(0xFFFFFFFFu, sq, o);
    }
    const int w = tid >> 5, lane = tid & 31;
    if (lane == 0) { red[w] = s; red[w + 8] = sq; }
    __syncthreads();
    if (tid == 0) {
        float S = 0.f, Q = 0.f;
#pragma unroll
        for (int i = 0; i < 8; i++) { S += red[i]; Q += red[i + 8]; }
        float mu  = S * (1.f / D_MODEL);
        float var = Q * (1.f / D_MODEL) - mu * mu;
        s_mu = mu; s_rstd = rsqrtf(var + EPSF);
    }
    __syncthreads();
    const float mu = s_mu, rstd = s_rstd;
    const float4 gv = ((const float4*)g)[tid];
    const float4 bv = ((const float4*)be)[tid];
    float o4[4];
    o4[0] = (v.x - mu) * rstd * gv.x + bv.x;
    o4[1] = (v.y - mu) * rstd * gv.y + bv.y;
    o4[2] = (v.z - mu) * rstd * gv.z + bv.z;
    o4[3] = (v.w - mu) * rstd * gv.w + bv.w;
    __nv_bfloat162* hp = (__nv_bfloat162*)(hi + (size_t)row * D_MODEL) + tid * 2;
    __nv_bfloat162* lp = (__nv_bfloat162*)(lo + (size_t)row * D_MODEL) + tid * 2;
#pragma unroll
    for (int j = 0; j < 2; j++) {
        uint32_t h, l;
        packsplit(o4[2 * j], o4[2 * j + 1], h, l);
        hp[j] = *(__nv_bfloat162*)&h;
        lp[j] = *(__nv_bfloat162*)&l;
    }
}

// ---------------------------------------------------------------------------
// Weight transpose + split
// ---------------------------------------------------------------------------
__global__ void transpose_split(const float* __restrict__ W,
                                __nv_bfloat16* __restrict__ hi, __nv_bfloat16* __restrict__ lo,
                                int K, int N) {
    __shared__ float t[32][33];
    const int k0 = blockIdx.y * 32, n0 = blockIdx.x * 32;
    const int tx = threadIdx.x & 31, ty = threadIdx.x >> 5;
#pragma unroll
    for (int i = 0; i < 32; i += 8)
        t[ty + i][tx] = W[(size_t)(k0 + ty + i) * N + n0 + tx];
    __syncthreads();
#pragma unroll
    for (int i = 0; i < 32; i += 8) {
        float v = t[tx][ty + i];
        __nv_bfloat16 h = __float2bfloat16(v);
        __nv_bfloat16 l = __float2bfloat16(v - __bfloat162float(h));
        hi[(size_t)(n0 + ty + i) * K + k0 + tx] = h;
        lo[(size_t)(n0 + ty + i) * K + k0 + tx] = l;
    }
}

// ---------------------------------------------------------------------------
// mma.sync bf16 split GEMM, 3-stage pipeline, ONE barrier per k-block.
// EPI: 0 = +bias fp32; 1 = +bias+res fp32; 2 = +bias gelu split;
//      3 = QKV: cols<1024 -> split bf16 (stride 1024), else fp32 (stride N)
// ---------------------------------------------------------------------------
#define TPAD_B   80
#define TILE_B   (128 * TPAD_B)
#define BUF_B    (4 * TILE_B)            // 40960
#define GM_SMEM  (3 * BUF_B)             // 122880

template<int EPI>
__global__ __launch_bounds__(256, 1)
void gemm_mma(const __nv_bfloat16* __restrict__ Ahi, const __nv_bfloat16* __restrict__ Alo,
              const __nv_bfloat16* __restrict__ Bhi, const __nv_bfloat16* __restrict__ Blo,
              const float* __restrict__ bias, const float* __restrict__ Res,
              float* __restrict__ C, __nv_bfloat16* __restrict__ Chi, __nv_bfloat16* __restrict__ Clo,
              int N, int K) {
    extern __shared__ char smc[];
    const uint32_t sb = s2u(smc);
    const int tid  = threadIdx.x;
    const int lane = tid & 31;
    const int wid  = tid >> 5;
    const int wm   = wid >> 2;
    const int wn   = wid & 3;
    const int bm = blockIdx.y * 128;
    const int bn = blockIdx.x * 128;

    const __nv_bfloat16* src0 = Ahi + (size_t)bm * K;
    const __nv_bfloat16* src1 = Alo + (size_t)bm * K;
    const __nv_bfloat16* src2 = Bhi + (size_t)bn * K;
    const __nv_bfloat16* src3 = Blo + (size_t)bn * K;

    const int r0 = tid >> 2,         c0 = tid & 3;
    const int r1 = (tid + 256) >> 2, c1 = tid & 3;

#define PREFETCH(kb, buf)                                                          \
    do {                                                                           \
        const uint32_t db = sb + (buf) * BUF_B;                                    \
        const int ko = (kb) * 32;                                                  \
        cp16(db + 0*TILE_B + r0*TPAD_B + c0*16, (const char*)(src0 + (size_t)r0*K + ko) + c0*16); \
        cp16(db + 0*TILE_B + r1*TPAD_B + c1*16, (const char*)(src0 + (size_t)r1*K + ko) + c1*16); \
        cp16(db + 1*TILE_B + r0*TPAD_B + c0*16, (const char*)(src1 + (size_t)r0*K + ko) + c0*16); \
        cp16(db + 1*TILE_B + r1*TPAD_B + c1*16, (const char*)(src1 + (size_t)r1*K + ko) + c1*16); \
        cp16(db + 2*TILE_B + r0*TPAD_B + c0*16, (const char*)(src2 + (size_t)r0*K + ko) + c0*16); \
        cp16(db + 2*TILE_B + r1*TPAD_B + c1*16, (const char*)(src2 + (size_t)r1*K + ko) + c1*16); \
        cp16(db + 3*TILE_B + r0*TPAD_B + c0*16, (const char*)(src3 + (size_t)r0*K + ko) + c0*16); \
        cp16(db + 3*TILE_B + r1*TPAD_B + c1*16, (const char*)(src3 + (size_t)r1*K + ko) + c1*16); \
        CP_COMMIT();                                                               \
    } while (0)

    float acc[4][4][4];
#pragma unroll
    for (int m = 0; m < 4; m++)
#pragma unroll
        for (int n = 0; n < 4; n++)
#pragma unroll
            for (int i = 0; i < 4; i++) acc[m][n][i] = 0.f;

    const int NKB = K >> 5;
    PREFETCH(0, 0);
    PREFETCH(1, 1);

    for (int kb = 0; kb < NKB; kb++) {
        if (kb + 2 < NKB) CP_WAIT(1); else CP_WAIT(0);
        __syncthreads();
        if (kb + 2 < NKB) PREFETCH(kb + 2, (kb + 2) % 3);

        const uint32_t b  = sb + (kb % 3) * BUF_B;
        const uint32_t Ah = b, Al = b + TILE_B, Bh = b + 2 * TILE_B, Bl = b + 3 * TILE_B;
#pragma unroll
        for (int ks = 0; ks < 2; ks++) {
            uint32_t ah[4][4], al[4][4], bh[2][4], bl[2][4];
            const uint32_t aoff  = (uint32_t)(wm * 64 + (lane & 15)) * TPAD_B + ks * 32 + (lane >> 4) * 16;
            const uint32_t boff4 = (uint32_t)(wn * 32 + (lane >> 4) * 8 + (lane & 7)) * TPAD_B
                                 + ks * 32 + ((lane >> 3) & 1) * 16;
#pragma unroll
            for (int m = 0; m < 4; m++) {
                ldsm4(ah[m], Ah + aoff + m * 16 * TPAD_B);
                ldsm4(al[m], Al + aoff + m * 16 * TPAD_B);
            }
#pragma unroll
            for (int p = 0; p < 2; p++) {
                ldsm4(bh[p], Bh + boff4 + p * 16 * TPAD_B);
                ldsm4(bl[p], Bl + boff4 + p * 16 * TPAD_B);
            }
#pragma unroll
            for (int m = 0; m < 4; m++)
#pragma unroll
                for (int n = 0; n < 4; n++) {
                    const uint32_t* bhn = &bh[n >> 1][(n & 1) * 2];
                    const uint32_t* bln = &bl[n >> 1][(n & 1) * 2];
                    mma16816(acc[m][n], ah[m], bhn);
                    mma16816(acc[m][n], al[m], bhn);
                    mma16816(acc[m][n], ah[m], bln);
                }
        }
    }

#pragma unroll
    for (int m = 0; m < 4; m++)
#pragma unroll
        for (int n = 0; n < 4; n++) {
            const int col  = bn + wn * 32 + n * 8 + 2 * (lane & 3);
            const float b0 = bias[col], b1 = bias[col + 1];
#pragma unroll
            for (int half = 0; half < 2; half++) {
                const int row = bm + wm * 64 + m * 16 + (lane >> 2) + half * 8;
                float v0 = acc[m][n][2 * half]     + b0;
                float v1 = acc[m][n][2 * half + 1] + b1;
                if (EPI == 2 || (EPI == 3 && bn < D_MODEL)) {
                    if (EPI == 2) {
                        v0 = 0.5f * v0 * (1.f + erff(v0 * 0.70710678118654752f));
                        v1 = 0.5f * v1 * (1.f + erff(v1 * 0.70710678118654752f));
                    }
                    const int stride = (EPI == 2) ? N : D_MODEL;
                    uint32_t h, l;
                    packsplit(v0, v1, h, l);
                    *(__nv_bfloat162*)(Chi + (size_t)row * stride + col) = *(__nv_bfloat162*)&h;
                    *(__nv_bfloat162*)(Clo + (size_t)row * stride + col) = *(__nv_bfloat162*)&l;
                } else {
                    if (EPI == 1) {
                        const float2 rv = *(const float2*)(Res + (size_t)row * N + col);
                        v0 += rv.x; v1 += rv.y;
                    }
                    float2 o2; o2.x = v0; o2.y = v1;
                    *(float2*)(C + (size_t)row * N + col) = o2;
                }
            }
        }
#undef PREFETCH
}

// ---------------------------------------------------------------------------
// Build K/V caches: fp32 to d_out, plus bf16 hi/lo splits for attention
// ---------------------------------------------------------------------------
__global__ void build_kv(const float* __restrict__ Kp, const float* __restrict__ Vp,
                         const float* __restrict__ qkv,
                         float* __restrict__ outK, float* __restrict__ outV) {
    const size_t PER = (size_t)BATCH * NHEAD * TK * HEAD_DIM / 4;
    size_t i = (size_t)blockIdx.x * blockDim.x + threadIdx.x;
    if (i >= 2 * PER) return;
    const int which = i >= PER;
    const size_t j = which ? (i - PER) : i;
    const size_t rowi = j >> 4;
    const int d4 = (int)(j & 15);
    const size_t bh = rowi >> 11;
    const int t = (int)(rowi & (TK - 1));
    float4 v;
    if (t < TP) {
        const float* src = (which ? Vp : Kp) + ((bh * TP + t) << 6) + (d4 << 2);
        v = *(const float4*)src;
    } else {
        const int h = (int)(bh & (NHEAD - 1));
        const size_t b = bh >> 4;
        const float* src = qkv + (b * TC + (t - TP)) * (size_t)(3 * D_MODEL)
                               + (which ? 2 * D_MODEL : D_MODEL) + h * HEAD_DIM + (d4 << 2);
        v = *(const float4*)src;
    }
    ((float4*)(which ? outV : outK))[rowi * 16 + d4] = v;
    uint32_t h01, l01, h23, l23;
    packsplit(v.x, v.y, h01, l01);
    packsplit(v.z, v.w, h23, l23);
    const size_t eb = rowi * 64 + (size_t)d4 * 4;
    __nv_bfloat162* Hp = (__nv_bfloat162*)((which ? g_Vbh : g_Kbh) + eb);
    __nv_bfloat162* Lp = (__nv_bfloat162*)((which ? g_Vbl : g_Kbl) + eb);
    Hp[0] = *(__nv_bfloat162*)&h01; Hp[1] = *(__nv_bfloat162*)&h23;
    Lp[0] = *(__nv_bfloat162*)&l01; Lp[1] = *(__nv_bfloat162*)&l23;
}

// ---------------------------------------------------------------------------
// Tensor-core flash attention: 128 q-rows per CTA, 8 warps (m16 each),
// 2-stage KV pipeline, one barrier per k-block, Q pre-split in gmem.
// ---------------------------------------------------------------------------
#define AQ_TILEB  18432                   // 128 rows * 144 B
#define AKV_TILEB 9216                    // 64 rows * 144 B
#define AKV_STAGE (4 * AKV_TILEB)         // Kh,Kl,Vh,Vl = 36864
#define AT_SMEM   (2 * AQ_TILEB + 2 * AKV_STAGE)   // 110592

__global__ __launch_bounds__(256, 1)
void attn_mma(const int* __restrict__ pos_ptr) {
    extern __shared__ char sma[];
    const uint32_t sbase = s2u(sma);
    const int tid = threadIdx.x, lane = tid & 31, w = tid >> 5;
    const int qb = blockIdx.x, bhid = blockIdx.y;
    const int b = bhid >> 4, h = bhid & 15;
    const int q0 = qb * 128;
    const int pos = *pos_ptr;
    const size_t kvbase = (size_t)bhid * TK * HEAD_DIM;
    const uint32_t kvs = sbase + 2 * AQ_TILEB;

#define AT_PRE(kb, bufi)                                                            \
    do {                                                                            \
        const size_t srcb = kvbase + (size_t)(kb) * 64 * 64;                        \
        const uint32_t db = kvs + (bufi) * AKV_STAGE;                               \
        _Pragma("unroll")                                                           \
        for (int t_ = 0; t_ < 2; t_++) {                                            \
            const int i_ = tid + t_ * 256;                                          \
            const int row_ = i_ >> 3; const int ch_ = (i_ & 7) * 16;                \
            const uint32_t doff = (uint32_t)row_ * 144 + ch_;                       \
            const size_t soff = srcb + (size_t)row_ * 64;                           \
            cp16(db + 0 * AKV_TILEB + doff, (const char*)(g_Kbh + soff) + ch_);     \
            cp16(db + 1 * AKV_TILEB + doff, (const char*)(g_Kbl + soff) + ch_);     \
            cp16(db + 2 * AKV_TILEB + doff, (const char*)(g_Vbh + soff) + ch_);     \
            cp16(db + 3 * AKV_TILEB + doff, (const char*)(g_Vbl + soff) + ch_);     \
        }                                                                           \
        CP_COMMIT();                                                                \
    } while (0)

    // prologue group: Q tile (hi+lo) + KV stage 0
    {
#pragma unroll
        for (int t_ = 0; t_ < 4; t_++) {
            const int i_ = tid + t_ * 256;            // 0..1023
            const int row_ = i_ >> 3; const int ch_ = (i_ & 7) * 16;
            const size_t soff = (size_t)(b * TC + q0 + row_) * D_MODEL + h * HEAD_DIM;
            cp16(sbase + row_ * 144 + ch_,            (const char*)(g_q_hi + soff) + ch_);
            cp16(sbase + AQ_TILEB + row_ * 144 + ch_, (const char*)(g_q_lo + soff) + ch_);
        }
        const size_t srcb = kvbase;
#pragma unroll
        for (int t_ = 0; t_ < 2; t_++) {
            const int i_ = tid + t_ * 256;
            const int row_ = i_ >> 3; const int ch_ = (i_ & 7) * 16;
            const uint32_t doff = (uint32_t)row_ * 144 + ch_;
            const size_t soff = srcb + (size_t)row_ * 64;
            cp16(kvs + 0 * AKV_TILEB + doff, (const char*)(g_Kbh + soff) + ch_);
            cp16(kvs + 1 * AKV_TILEB + doff, (const char*)(g_Kbl + soff) + ch_);
            cp16(kvs + 2 * AKV_TILEB + doff, (const char*)(g_Vbh + soff) + ch_);
            cp16(kvs + 3 * AKV_TILEB + doff, (const char*)(g_Vbl + soff) + ch_);
        }
        CP_COMMIT();
    }

    float oacc[8][4];
#pragma unroll
    for (int nb = 0; nb < 8; nb++)
#pragma unroll
        for (int i = 0; i < 4; i++) oacc[nb][i] = 0.f;
    float m0 = -1e30f, m1 = -1e30f, l0 = 0.f, l1 = 0.f;

    const int r0 = lane >> 2;
    const int lim0 = pos + q0 + w * 16 + r0;
    const int lim1 = lim0 + 8;
    const int warp_lim = pos + q0 + w * 16;
    const int nkb = (pos + q0 + 191) >> 6;

    const uint32_t aoff0 = (uint32_t)(w * 16 + (lane & 15)) * 144 + (lane >> 4) * 16;
    const uint32_t koff0 = (uint32_t)((lane >> 4) * 8 + (lane & 7)) * 144 + ((lane >> 3) & 1) * 16;

    for (int kb = 0; kb < nkb; kb++) {
        CP_WAIT(0);
        __syncthreads();
        if (kb + 1 < nkb) AT_PRE(kb + 1, (kb + 1) & 1);

        const uint32_t bb = kvs + (kb & 1) * AKV_STAGE;
        const uint32_t Kh = bb, Kl = bb + AKV_TILEB, Vh = bb + 2 * AKV_TILEB, Vl = bb + 3 * AKV_TILEB;

        // ---- S = Q K^T ----
        float sacc[8][4];
#pragma unroll
        for (int nb = 0; nb < 8; nb++)
#pragma unroll
            for (int i = 0; i < 4; i++) sacc[nb][i] = 0.f;
#pragma unroll
        for (int ks = 0; ks < 4; ks++) {
            uint32_t ah[4], al[4], kh[4][4], kl[4][4];
            ldsm4(ah, sbase + aoff0 + ks * 32);
            ldsm4(al, sbase + AQ_TILEB + aoff0 + ks * 32);
#pragma unroll
            for (int p = 0; p < 4; p++) {
                ldsm4(kh[p], Kh + koff0 + ks * 32 + p * 16 * 144);
                ldsm4(kl[p], Kl + koff0 + ks * 32 + p * 16 * 144);
            }
#pragma unroll
            for (int nb = 0; nb < 8; nb++) {
                const uint32_t* khn = &kh[nb >> 1][(nb & 1) * 2];
                const uint32_t* kln = &kl[nb >> 1][(nb & 1) * 2];
                mma16816(sacc[nb], ah, khn);
                mma16816(sacc[nb], al, khn);
                mma16816(sacc[nb], ah, kln);
            }
        }

        // ---- scale + mask ----
        const int kstart = kb * 64;
        if (kstart + 63 <= warp_lim) {
#pragma unroll
            for (int nb = 0; nb < 8; nb++)
#pragma unroll
                for (int i = 0; i < 4; i++) sacc[nb][i] *= 0.125f;
        } else {
#pragma unroll
            for (int nb = 0; nb < 8; nb++) {
                const int tok = kstart + nb * 8 + 2 * (lane & 3);
                sacc[nb][0] = (tok     <= lim0) ? sacc[nb][0] * 0.125f : -1e30f;
                sacc[nb][1] = (tok + 1 <= lim0) ? sacc[nb][1] * 0.125f : -1e30f;
                sacc[nb][2] = (tok     <= lim1) ? sacc[nb][2] * 0.125f : -1e30f;
                sacc[nb][3] = (tok + 1 <= lim1) ? sacc[nb][3] * 0.125f : -1e30f;
            }
        }

        // ---- online softmax ----
        float mx0 = -1e30f, mx1 = -1e30f;
#pragma unroll
        for (int nb = 0; nb < 8; nb++) {
            mx0 = fmaxf(mx0, fmaxf(sacc[nb][0], sacc[nb][1]));
            mx1 = fmaxf(mx1, fmaxf(sacc[nb][2], sacc[nb][3]));
        }
        mx0 = fmaxf(mx0, __shfl_xor_sync(0xFFFFFFFFu, mx0, 1));
        mx0 = fmaxf(mx0, __shfl_xor_sync(0xFFFFFFFFu, mx0, 2));
        mx1 = fmaxf(mx1, __shfl_xor_sync(0xFFFFFFFFu, mx1, 1));
        mx1 = fmaxf(mx1, __shfl_xor_sync(0xFFFFFFFFu, mx1, 2));
        const float mn0 = fmaxf(m0, mx0), mn1 = fmaxf(m1, mx1);
        const float al0 = __expf(m0 - mn0), al1 = __expf(m1 - mn1);
        m0 = mn0; m1 = mn1;
        float ls0 = 0.f, ls1 = 0.f;
#pragma unroll
        for (int nb = 0; nb < 8; nb++) {
            sacc[nb][0] = __expf(sacc[nb][0] - mn0);
            sacc[nb][1] = __expf(sacc[nb][1] - mn0);
            sacc[nb][2] = __expf(sacc[nb][2] - mn1);
            sacc[nb][3] = __expf(sacc[nb][3] - mn1);
            ls0 += sacc[nb][0] + sacc[nb][1];
            ls1 += sacc[nb][2] + sacc[nb][3];
        }
        ls0 += __shfl_xor_sync(0xFFFFFFFFu, ls0, 1);
        ls0 += __shfl_xor_sync(0xFFFFFFFFu, ls0, 2);
        ls1 += __shfl_xor_sync(0xFFFFFFFFu, ls1, 1);
        ls1 += __shfl_xor_sync(0xFFFFFFFFu, ls1, 2);
        l0 = l0 * al0 + ls0;
        l1 = l1 * al1 + ls1;
#pragma unroll
        for (int nb = 0; nb < 8; nb++) {
            oacc[nb][0] *= al0; oacc[nb][1] *= al0;
            oacc[nb][2] *= al1; oacc[nb][3] *= al1;
        }

        // ---- O += P V ----
#pragma unroll
        for (int ks = 0; ks < 4; ks++) {
            uint32_t phi[4], plo[4];
            packsplit(sacc[2 * ks][0],     sacc[2 * ks][1],     phi[0], plo[0]);
            packsplit(sacc[2 * ks][2],     sacc[2 * ks][3],     phi[1], plo[1]);
            packsplit(sacc[2 * ks + 1][0], sacc[2 * ks + 1][1], phi[2], plo[2]);
            packsplit(sacc[2 * ks + 1][2], sacc[2 * ks + 1][3], phi[3], plo[3]);
            const uint32_t voff4 = (uint32_t)(ks * 16 + (lane & 15)) * 144 + (lane >> 4) * 16;
            uint32_t vh[4][4], vl[4][4];
#pragma unroll
            for (int p = 0; p < 4; p++) {
                ldsm4t(vh[p], Vh + voff4 + p * 32);
                ldsm4t(vl[p], Vl + voff4 + p * 32);
            }
#pragma unroll
            for (int nb = 0; nb < 8; nb++) {
                const uint32_t* vhn = &vh[nb >> 1][(nb & 1) * 2];
                const uint32_t* vln = &vl[nb >> 1][(nb & 1) * 2];
                mma16816(oacc[nb], phi, vhn);
                mma16816(oacc[nb], plo, vhn);
                mma16816(oacc[nb], phi, vln);
            }
        }
    }

    // ---- epilogue ----
    const float inv0 = 1.f / l0, inv1 = 1.f / l1;
    const int grow0 = b * TC + q0 + w * 16 + r0;
#pragma unroll
    for (int nb = 0; nb < 8; nb++) {
        const int col = h * HEAD_DIM + nb * 8 + 2 * (lane & 3);
        uint32_t hh, ll;
        packsplit(oacc[nb][0] * inv0, oacc[nb][1] * inv0, hh, ll);
        *(__nv_bfloat162*)(g_o_hi + (size_t)grow0 * D_MODEL + col) = *(__nv_bfloat162*)&hh;
        *(__nv_bfloat162*)(g_o_lo + (size_t)grow0 * D_MODEL + col) = *(__nv_bfloat162*)&ll;
        packsplit(oacc[nb][2] * inv1, oacc[nb][3] * inv1, hh, ll);
        *(__nv_bfloat162*)(g_o_hi + (size_t)(grow0 + 8) * D_MODEL + col) = *(__nv_bfloat162*)&hh;
        *(__nv_bfloat162*)(g_o_lo + (size_t)(grow0 + 8) * D_MODEL + col) = *(__nv_bfloat162*)&ll;
    }
#undef AT_PRE
}

// ---------------------------------------------------------------------------
// Launch
// ---------------------------------------------------------------------------
extern "C" void kernel_launch(void* const* d_in, const int* in_sizes, int n_in,
                              void* d_out, int out_size) {
    const float* x    = (const float*)d_in[0];
    const float* Kp   = (const float*)d_in[1];
    const float* Vp   = (const float*)d_in[2];
    const int*   posp = (const int*)  d_in[3];
    const float* wqkv = (const float*)d_in[4];
    const float* bqkv = (const float*)d_in[5];
    const float* wo   = (const float*)d_in[6];
    const float* bo   = (const float*)d_in[7];
    const float* g1   = (const float*)d_in[8];
    const float* be1  = (const float*)d_in[9];
    const float* g2   = (const float*)d_in[10];
    const float* be2  = (const float*)d_in[11];
    const float* w1   = (const float*)d_in[12];
    const float* bf1  = (const float*)d_in[13];
    const float* w2   = (const float*)d_in[14];
    const float* bf2  = (const float*)d_in[15];

    float* out_x = (float*)d_out;
    float* out_K = out_x + (size_t)BATCH * TC * D_MODEL;
    float* out_V = out_K + (size_t)BATCH * NHEAD * TK * HEAD_DIM;

    void* p;
    cudaGetSymbolAddress(&p, g_qkv);      float* qkv = (float*)p;
    cudaGetSymbolAddress(&p, g_x1);       float* x1  = (float*)p;
    cudaGetSymbolAddress(&p, g_h_hi);     __nv_bfloat16* hhi = (__nv_bfloat16*)p;
    cudaGetSymbolAddress(&p, g_h_lo);     __nv_bfloat16* hlo = (__nv_bfloat16*)p;
    cudaGetSymbolAddress(&p, g_q_hi);     __nv_bfloat16* qhi = (__nv_bfloat16*)p;
    cudaGetSymbolAddress(&p, g_q_lo);     __nv_bfloat16* qlo = (__nv_bfloat16*)p;
    cudaGetSymbolAddress(&p, g_o_hi);     __nv_bfloat16* ohi = (__nv_bfloat16*)p;
    cudaGetSymbolAddress(&p, g_o_lo);     __nv_bfloat16* olo = (__nv_bfloat16*)p;
    cudaGetSymbolAddress(&p, g_h2_hi);    __nv_bfloat16* h2hi = (__nv_bfloat16*)p;
    cudaGetSymbolAddress(&p, g_h2_lo);    __nv_bfloat16* h2lo = (__nv_bfloat16*)p;
    cudaGetSymbolAddress(&p, g_ff_hi);    __nv_bfloat16* ffhi = (__nv_bfloat16*)p;
    cudaGetSymbolAddress(&p, g_ff_lo);    __nv_bfloat16* fflo = (__nv_bfloat16*)p;
    cudaGetSymbolAddress(&p, g_wqkvT_hi); __nv_bfloat16* wqkvThi = (__nv_bfloat16*)p;
    cudaGetSymbolAddress(&p, g_wqkvT_lo); __nv_bfloat16* wqkvTlo = (__nv_bfloat16*)p;
    cudaGetSymbolAddress(&p, g_woT_hi);   __nv_bfloat16* woThi = (__nv_bfloat16*)p;
    cudaGetSymbolAddress(&p, g_woT_lo);   __nv_bfloat16* woTlo = (__nv_bfloat16*)p;
    cudaGetSymbolAddress(&p, g_w1T_hi);   __nv_bfloat16* w1Thi = (__nv_bfloat16*)p;
    cudaGetSymbolAddress(&p, g_w1T_lo);   __nv_bfloat16* w1Tlo = (__nv_bfloat16*)p;
    cudaGetSymbolAddress(&p, g_w2T_hi);   __nv_bfloat16* w2Thi = (__nv_bfloat16*)p;
    cudaGetSymbolAddress(&p, g_w2T_lo);   __nv_bfloat16* w2Tlo = (__nv_bfloat16*)p;

    cudaFuncSetAttribute(attn_mma, cudaFuncAttributeMaxDynamicSharedMemorySize, AT_SMEM);
    cudaFuncSetAttribute(gemm_mma<0>, cudaFuncAttributeMaxDynamicSharedMemorySize, GM_SMEM);
    cudaFuncSetAttribute(gemm_mma<1>, cudaFuncAttributeMaxDynamicSharedMemorySize, GM_SMEM);
    cudaFuncSetAttribute(gemm_mma<2>, cudaFuncAttributeMaxDynamicSharedMemorySize, GM_SMEM);
    cudaFuncSetAttribute(gemm_mma<3>, cudaFuncAttributeMaxDynamicSharedMemorySize, GM_SMEM);

    // ordering chosen so the ncu capture slot lands on real kernels
    transpose_split<<<dim3(3 * D_MODEL / 32, D_MODEL / 32), 256>>>(wqkv, wqkvThi, wqkvTlo, D_MODEL, 3 * D_MODEL);
    ln_split_kernel<<<NROWS, 256>>>(x, g1, be1, hhi, hlo);
    // QKV GEMM: Q -> split bf16, K/V -> fp32 qkv
    gemm_mma<3><<<dim3(3 * D_MODEL / 128, NROWS / 128), 256, GM_SMEM>>>(
        hhi, hlo, wqkvThi, wqkvTlo, bqkv, nullptr, qkv, qhi, qlo, 3 * D_MODEL, D_MODEL);
    build_kv<<<16384, 256>>>(Kp, Vp, qkv, out_K, out_V);
    attn_mma<<<dim3(TC / 128, BATCH * NHEAD), 256, AT_SMEM>>>(posp);
    transpose_split<<<dim3(D_MODEL / 32, D_MODEL / 32), 256>>>(wo, woThi, woTlo, D_MODEL, D_MODEL);
    gemm_mma<1><<<dim3(D_MODEL / 128, NROWS / 128), 256, GM_SMEM>>>(
        ohi, olo, woThi, woTlo, bo, x, x1, nullptr, nullptr, D_MODEL, D_MODEL);
    ln_split_kernel<<<NROWS, 256>>>(x1, g2, be2, h2hi, h2lo);
    transpose_split<<<dim3(DIM_FF / 32, D_MODEL / 32), 256>>>(w1, w1Thi, w1Tlo, D_MODEL, DIM_FF);
    gemm_mma<2><<<dim3(DIM_FF / 128, NROWS / 128), 256, GM_SMEM>>>(
        h2hi, h2lo, w1Thi, w1Tlo, bf1, nullptr, nullptr, ffhi, fflo, DIM_FF, D_MODEL);
    transpose_split<<<dim3(D_MODEL / 32, DIM_FF / 32), 256>>>(w2, w2Thi, w2Tlo, DIM_FF, D_MODEL);
    gemm_mma<1><<<dim3(D_MODEL / 128, NROWS / 128), 256, GM_SMEM>>>(
        ffhi, fflo, w2Thi, w2Tlo, bf2, x1, out_x, nullptr, nullptr, D_MODEL, DIM_FF);
}